// round 3
// baseline (speedup 1.0000x reference)
#include <cuda_runtime.h>

#define NNODES 20000
#define NEDGES 640000
#define DINF   92
#define CF     128
#define NCF    (NNODES*CF)

// ---------------- scratch (device globals; no allocation) ----------------
__device__ __align__(16) float g_X[NCF];          // node features through encoder
__device__ __align__(16) float g_T[NCF];          // pre-BN temp
__device__ __align__(16) float g_Hb[NCF];         // GIN aggregated
__device__ __align__(16) float g_HHb[NNODES*256]; // GAT hh [N, H*C]
__device__ __align__(16) float g_AGG[NNODES*256]; // GAT aggregated
__device__ __align__(16) float g_ZOUT[NCF];
__device__ __align__(16) float g_AS[NNODES*2];
__device__ __align__(16) float g_AD[NNODES*2];
__device__ __align__(16) float g_S1[CF];
__device__ __align__(16) float g_S2[CF];
__device__ __align__(16) float g_cs[CF];
__device__ __align__(16) float g_cb[CF];
__device__ int   g_cnt[NNODES];
__device__ int   g_rowptr[NNODES+1];
__device__ int   g_cursor[NNODES];
__device__ int   g_csrc[NEDGES];
__device__ int   g_is64;

// ---------------- edge index dtype sniffing ----------------
// JAX may emit int32 (x64 disabled) or int64. If int64 (values < 2^31, >=0),
// every odd int32 word of the first half is zero.
__global__ void detect_kernel(const void* idx) {
    const int* w = (const int*)idx;
    __shared__ int nz;
    if (threadIdx.x == 0) nz = 0;
    __syncthreads();
    for (int i = threadIdx.x; i < 4096; i += blockDim.x) {
        long long pos = 2LL * i * (NEDGES / 4096) + 1;   // < 2*NEDGES
        if (pos < 2LL * NEDGES && w[pos] != 0) atomicOr(&nz, 1);
    }
    __syncthreads();
    if (threadIdx.x == 0) g_is64 = (nz == 0) ? 1 : 0;
}

__device__ __forceinline__ int edge_src(const void* p, int e) {
    return g_is64 ? (int)((const long long*)p)[e] : ((const int*)p)[e];
}
__device__ __forceinline__ int edge_dst(const void* p, int e) {
    return g_is64 ? (int)((const long long*)p)[NEDGES + e] : ((const int*)p)[NEDGES + e];
}

// ---------------- CSR build ----------------
__global__ void zero_cnt_kernel() {
    int i = blockIdx.x * blockDim.x + threadIdx.x;
    if (i < NNODES) g_cnt[i] = 0;
}
__global__ void hist_kernel(const void* eidx) {
    int e = blockIdx.x * blockDim.x + threadIdx.x;
    if (e < NEDGES) atomicAdd(&g_cnt[edge_dst(eidx, e)], 1);
}
__global__ void scan_kernel() {   // 1 block, 1024 threads
    __shared__ int warp_sums[32];
    __shared__ int s_carry;
    int tid = threadIdx.x, lane = tid & 31, wid = tid >> 5;
    if (tid == 0) s_carry = 0;
    __syncthreads();
    for (int base = 0; base < NNODES; base += 1024) {
        int i = base + tid;
        int v = (i < NNODES) ? g_cnt[i] : 0;
        int x = v;
        #pragma unroll
        for (int o = 1; o < 32; o <<= 1) {
            int y = __shfl_up_sync(0xffffffffu, x, o);
            if (lane >= o) x += y;
        }
        if (lane == 31) warp_sums[wid] = x;
        __syncthreads();
        if (wid == 0) {
            int ws = warp_sums[lane];
            #pragma unroll
            for (int o = 1; o < 32; o <<= 1) {
                int y = __shfl_up_sync(0xffffffffu, ws, o);
                if (lane >= o) ws += y;
            }
            warp_sums[lane] = ws;
        }
        __syncthreads();
        int incl = x + (wid > 0 ? warp_sums[wid - 1] : 0) + s_carry;
        int excl = incl - v;
        if (i < NNODES) { g_rowptr[i] = excl; g_cursor[i] = excl; }
        __syncthreads();
        if (tid == 1023) s_carry = incl;
        __syncthreads();
    }
    if (threadIdx.x == 0) g_rowptr[NNODES] = s_carry;
}
__global__ void scatter_kernel(const void* eidx) {
    int e = blockIdx.x * blockDim.x + threadIdx.x;
    if (e < NEDGES) {
        int d = edge_dst(eidx, e);
        int s = edge_src(eidx, e);
        int p = atomicAdd(&g_cursor[d], 1);
        g_csrc[p] = s;
    }
}

// ---------------- GEMM: Out[M,Ntot] = act(A)[M,K] @ B[K,Ntot] + bias ----------------
// Block computes 64 rows x 128 cols (col block via blockIdx.y). Optional per-K
// affine+relu applied to A on load (fused BN+ReLU), optional per-column
// sum/sumsq accumulation (fused BN stats) into g_S1/g_S2.
__global__ void __launch_bounds__(256)
gemm_kernel(const float* __restrict__ A, int lda, int K, int M,
            const float* __restrict__ B, int ldb,
            const float* __restrict__ bias,
            float* __restrict__ Out, int ldo,
            const float* __restrict__ affs, const float* __restrict__ affb,
            int do_stats)
{
    __shared__ float As[64][68];     // [k][m]; row stride 272B = 16B-aligned
    __shared__ float Bs[64][128];    // [k][n]
    __shared__ float s1[128], s2[128];

    int tid = threadIdx.x;
    int tx = tid & 15, ty = tid >> 4;
    int r0 = blockIdx.x * 64;
    int c0 = blockIdx.y * 128;

    float acc[4][8];
    #pragma unroll
    for (int i = 0; i < 4; i++)
        #pragma unroll
        for (int j = 0; j < 8; j++) acc[i][j] = 0.f;

    for (int kt = 0; kt < K; kt += 64) {
        // load A tile (scalar; handles lda=92)
        #pragma unroll
        for (int pass = 0; pass < 4; pass++) {
            int ar  = (tid >> 4) + pass * 16;
            int row = r0 + ar;
            int kk  = (tid & 15) * 4;
            #pragma unroll
            for (int i = 0; i < 4; i++) {
                int k = kt + kk + i;
                float x = 0.f;
                if (row < M && k < K) {
                    x = A[row * lda + k];
                    if (affs) x = fmaxf(affs[k] * x + affb[k], 0.f);
                }
                As[kk + i][ar] = x;
            }
        }
        // load B tile (vector)
        #pragma unroll
        for (int pass = 0; pass < 8; pass++) {
            int kr  = (tid >> 5) + pass * 8;
            int col = (tid & 31) * 4;
            float4 bv = make_float4(0.f, 0.f, 0.f, 0.f);
            int k = kt + kr;
            if (k < K) bv = *(const float4*)&B[k * ldb + c0 + col];
            *(float4*)&Bs[kr][col] = bv;
        }
        __syncthreads();
        #pragma unroll 8
        for (int kk = 0; kk < 64; kk++) {
            float4 a4 = *(float4*)&As[kk][ty * 4];
            float4 b0 = *(float4*)&Bs[kk][tx * 4];
            float4 b1 = *(float4*)&Bs[kk][64 + tx * 4];
            float av[4] = {a4.x, a4.y, a4.z, a4.w};
            float bv[8] = {b0.x, b0.y, b0.z, b0.w, b1.x, b1.y, b1.z, b1.w};
            #pragma unroll
            for (int i = 0; i < 4; i++)
                #pragma unroll
                for (int j = 0; j < 8; j++)
                    acc[i][j] += av[i] * bv[j];
        }
        __syncthreads();
    }

    // epilogue: cols for thread are {tx*4+j}j<4 and {64+tx*4+j-4}j>=4
    float bcol[8];
    #pragma unroll
    for (int j = 0; j < 8; j++) {
        int c = (j < 4) ? (tx * 4 + j) : (64 + tx * 4 + j - 4);
        bcol[j] = bias ? bias[c0 + c] : 0.f;
    }
    #pragma unroll
    for (int i = 0; i < 4; i++) {
        int row = r0 + ty * 4 + i;
        if (row < M) {
            #pragma unroll
            for (int j = 0; j < 8; j++) {
                int c = (j < 4) ? (tx * 4 + j) : (64 + tx * 4 + j - 4);
                Out[row * ldo + c0 + c] = acc[i][j] + bcol[j];
            }
        }
    }
    if (do_stats) {
        if (tid < 128) { s1[tid] = 0.f; s2[tid] = 0.f; }
        __syncthreads();
        #pragma unroll
        for (int j = 0; j < 8; j++) {
            int c = (j < 4) ? (tx * 4 + j) : (64 + tx * 4 + j - 4);
            float sv = 0.f, sq = 0.f;
            #pragma unroll
            for (int i = 0; i < 4; i++) {
                int row = r0 + ty * 4 + i;
                if (row < M) { float v = acc[i][j] + bcol[j]; sv += v; sq += v * v; }
            }
            atomicAdd(&s1[c], sv);
            atomicAdd(&s2[c], sq);
        }
        __syncthreads();
        if (tid < 128) { atomicAdd(&g_S1[tid], s1[tid]); atomicAdd(&g_S2[tid], s2[tid]); }
    }
}

// ---------------- BN ----------------
__global__ void zero_stats_kernel() {
    int i = threadIdx.x;
    if (i < CF) { g_S1[i] = 0.f; g_S2[i] = 0.f; }
}
__global__ void bn_fin_kernel(const float* __restrict__ gam, const float* __restrict__ bet) {
    int c = threadIdx.x;
    if (c < CF) {
        float mu  = g_S1[c] / (float)NNODES;
        float var = g_S2[c] / (float)NNODES - mu * mu;
        float a   = gam[c] * rsqrtf(var + 1e-5f);
        g_cs[c] = a;
        g_cb[c] = bet[c] - mu * a;
    }
}
__global__ void apply_bnrelu_kernel() {   // g_X = relu(cs*g_T+cb)
    int i = blockIdx.x * blockDim.x + threadIdx.x;
    if (i < NCF) {
        int c = i & 127;
        g_X[i] = fmaxf(g_cs[c] * g_T[i] + g_cb[c], 0.f);
    }
}

// ---------------- GIN aggregation: g_Hb[n] = g_X[n] + sum_in g_X[src] ----------------
__global__ void gin_agg_kernel() {
    int warp = (blockIdx.x * blockDim.x + threadIdx.x) >> 5;
    int lane = threadIdx.x & 31;
    if (warp >= NNODES) return;
    int n = warp;
    float4 acc = *(const float4*)&g_X[n * CF + lane * 4];
    int beg = g_rowptr[n], end = g_rowptr[n + 1];
    int i = beg;
    for (; i + 1 < end; i += 2) {
        int s0 = g_csrc[i], s1v = g_csrc[i + 1];
        float4 v0 = *(const float4*)&g_X[s0 * CF + lane * 4];
        float4 v1 = *(const float4*)&g_X[s1v * CF + lane * 4];
        acc.x += v0.x + v1.x; acc.y += v0.y + v1.y;
        acc.z += v0.z + v1.z; acc.w += v0.w + v1.w;
    }
    if (i < end) {
        int s0 = g_csrc[i];
        float4 v0 = *(const float4*)&g_X[s0 * CF + lane * 4];
        acc.x += v0.x; acc.y += v0.y; acc.z += v0.z; acc.w += v0.w;
    }
    *(float4*)&g_Hb[n * CF + lane * 4] = acc;
}

// ---------------- z = eps*exp(0.5*logvar)+mu ----------------
__global__ void z_kernel(const float* __restrict__ eps, float* __restrict__ out) {
    int i = blockIdx.x * blockDim.x + threadIdx.x;
    if (i < NCF) {
        float mu = out[2 * NCF + i];
        float lv = out[3 * NCF + i];
        out[i] = eps[i] * expf(0.5f * lv) + mu;
    }
}

// ---------------- GAT attention scalars ----------------
__global__ void asad_kernel(const float* __restrict__ att_s, const float* __restrict__ att_d) {
    int warp = (blockIdx.x * blockDim.x + threadIdx.x) >> 5;
    int lane = threadIdx.x & 31;
    if (warp >= NNODES) return;
    int n = warp, h = lane >> 4, sub = lane & 15;
    const float* hr  = &g_HHb[n * 256 + h * 128 + sub * 8];
    const float* asv = &att_s[h * 128 + sub * 8];
    const float* adv = &att_d[h * 128 + sub * 8];
    float ss = 0.f, sd = 0.f;
    #pragma unroll
    for (int j = 0; j < 8; j++) { float v = hr[j]; ss += v * asv[j]; sd += v * adv[j]; }
    #pragma unroll
    for (int o = 8; o >= 1; o >>= 1) {
        ss += __shfl_xor_sync(0xffffffffu, ss, o);
        sd += __shfl_xor_sync(0xffffffffu, sd, o);
    }
    if (sub == 0) { g_AS[n * 2 + h] = ss; g_AD[n * 2 + h] = sd; }
}

__device__ __forceinline__ float lrelu(float x) { return x > 0.f ? x : 0.2f * x; }

// ---------------- GAT aggregation w/ segment softmax (one warp per node,head) ----------------
__global__ void gat_agg_kernel(const float* __restrict__ b_gat) {
    int warp = (blockIdx.x * blockDim.x + threadIdx.x) >> 5;
    int lane = threadIdx.x & 31;
    if (warp >= NNODES * 2) return;
    int n = warp >> 1, h = warp & 1;
    float adn   = g_AD[n * 2 + h];
    float lself = lrelu(g_AS[n * 2 + h] + adn);
    int beg = g_rowptr[n], end = g_rowptr[n + 1];

    // pass 1: segment max (incl. self-loop)
    float m = lself;
    for (int i = beg + lane; i < end; i += 32) {
        int s = g_csrc[i];
        m = fmaxf(m, lrelu(g_AS[s * 2 + h] + adn));
    }
    #pragma unroll
    for (int o = 16; o >= 1; o >>= 1) m = fmaxf(m, __shfl_xor_sync(0xffffffffu, m, o));

    // pass 2: weighted accumulate (all lanes lockstep over edges)
    float w = expf(lself - m);
    float ssum = w;
    float4 hv = *(const float4*)&g_HHb[n * 256 + h * 128 + lane * 4];
    float4 acc = make_float4(w * hv.x, w * hv.y, w * hv.z, w * hv.w);
    for (int i = beg; i < end; i++) {
        int s = g_csrc[i];
        float l  = lrelu(g_AS[s * 2 + h] + adn);
        float we = expf(l - m);
        ssum += we;
        float4 v = *(const float4*)&g_HHb[s * 256 + h * 128 + lane * 4];
        acc.x += we * v.x; acc.y += we * v.y; acc.z += we * v.z; acc.w += we * v.w;
    }
    float inv = 1.f / ssum;
    float4 bg = *(const float4*)&b_gat[h * 128 + lane * 4];
    float4 o4 = make_float4(acc.x * inv + bg.x, acc.y * inv + bg.y,
                            acc.z * inv + bg.z, acc.w * inv + bg.w);
    *(float4*)&g_AGG[n * 256 + h * 128 + lane * 4] = o4;
}

// ---------------- host orchestration ----------------
extern "C" void kernel_launch(void* const* d_in, const int* in_sizes, int n_in,
                              void* d_out, int out_size) {
    const float* nf     = (const float*)d_in[0];
    const void*  eidx   =               d_in[1];
    const float* eps    = (const float*)d_in[2];
    const float* W_emb  = (const float*)d_in[3];
    const float* b_emb  = (const float*)d_in[4];
    const float* g_emb  = (const float*)d_in[5];
    const float* be_emb = (const float*)d_in[6];
    const float* W1     = (const float*)d_in[7];
    const float* b1     = (const float*)d_in[8];
    const float* g1     = (const float*)d_in[9];
    const float* be1    = (const float*)d_in[10];
    const float* W2     = (const float*)d_in[11];
    const float* b2     = (const float*)d_in[12];
    const float* W_mu   = (const float*)d_in[13];
    const float* b_mu   = (const float*)d_in[14];
    const float* W_var  = (const float*)d_in[15];
    const float* b_var  = (const float*)d_in[16];
    const float* W_gat  = (const float*)d_in[17];
    const float* att_s  = (const float*)d_in[18];
    const float* att_d  = (const float*)d_in[19];
    const float* b_gat  = (const float*)d_in[20];
    const float* W_dec  = (const float*)d_in[21];
    const float* b_dec  = (const float*)d_in[22];
    float* out = (float*)d_out;

    float *X, *T, *Hb, *HHp, *AGG, *ZOUT, *CS, *CB;
    cudaGetSymbolAddress((void**)&X,    g_X);
    cudaGetSymbolAddress((void**)&T,    g_T);
    cudaGetSymbolAddress((void**)&Hb,   g_Hb);
    cudaGetSymbolAddress((void**)&HHp,  g_HHb);
    cudaGetSymbolAddress((void**)&AGG,  g_AGG);
    cudaGetSymbolAddress((void**)&ZOUT, g_ZOUT);
    cudaGetSymbolAddress((void**)&CS,   g_cs);
    cudaGetSymbolAddress((void**)&CB,   g_cb);

    const int MB = (NNODES + 63) / 64;   // 313
    dim3 grid1(MB, 1), grid2(MB, 2);
    const int EB = (NEDGES + 255) / 256;
    const int NB = (NNODES + 255) / 256;
    const int WARP_N  = (NNODES * 32 + 255) / 256;     // 1 warp / node
    const int WARP_2N = (NNODES * 2 * 32 + 255) / 256; // 1 warp / (node,head)
    const int ELB = (NCF + 255) / 256;

    // CSR build (once per launch)
    detect_kernel<<<1, 256>>>(eidx);
    zero_cnt_kernel<<<NB, 256>>>();
    hist_kernel<<<EB, 256>>>(eidx);
    scan_kernel<<<1, 1024>>>();
    scatter_kernel<<<EB, 256>>>(eidx);

    // atom embedding: T = nf@W_emb+b (w/ stats); X = relu(bn(T))
    zero_stats_kernel<<<1, 128>>>();
    gemm_kernel<<<grid1, 256>>>(nf, DINF, DINF, NNODES, W_emb, CF, b_emb, T, CF,
                                nullptr, nullptr, 1);
    bn_fin_kernel<<<1, 128>>>(g_emb, be_emb);
    apply_bnrelu_kernel<<<ELB, 256>>>();

    // GIN encoder x2 (shared weights)
    for (int l = 0; l < 2; l++) {
        gin_agg_kernel<<<WARP_N, 256>>>();
        zero_stats_kernel<<<1, 128>>>();
        gemm_kernel<<<grid1, 256>>>(Hb, CF, CF, NNODES, W1, CF, b1, T, CF,
                                    nullptr, nullptr, 1);
        bn_fin_kernel<<<1, 128>>>(g1, be1);
        gemm_kernel<<<grid1, 256>>>(T, CF, CF, NNODES, W2, CF, b2, X, CF,
                                    CS, CB, 0);   // fused relu(bn(T)) on A-load
    }

    // VAE heads -> mu, logvar straight into d_out, then z into zin region
    gemm_kernel<<<grid1, 256>>>(X, CF, CF, NNODES, W_mu, CF, b_mu, out + 2 * NCF, CF,
                                nullptr, nullptr, 0);
    gemm_kernel<<<grid1, 256>>>(X, CF, CF, NNODES, W_var, CF, b_var, out + 3 * NCF, CF,
                                nullptr, nullptr, 0);
    z_kernel<<<ELB, 256>>>(eps, out);

    // GAT decoder x2 (shared weights)
    for (int l = 0; l < 2; l++) {
        const float* zcur = (l == 0) ? out : ZOUT;       // zin region then ZOUT
        float* zdst       = (l == 0) ? ZOUT : out + NCF; // ZOUT then zout region
        gemm_kernel<<<grid2, 256>>>(zcur, CF, CF, NNODES, W_gat, 256, nullptr, HHp, 256,
                                    nullptr, nullptr, 0);
        asad_kernel<<<WARP_N, 256>>>(att_s, att_d);
        gat_agg_kernel<<<WARP_2N, 256>>>(b_gat);
        gemm_kernel<<<grid1, 256>>>(AGG, 256, 256, NNODES, W_dec, CF, b_dec, zdst, CF,
                                    nullptr, nullptr, 0);
    }
    (void)in_sizes; (void)n_in; (void)out_size;
}

// round 4
// speedup vs baseline: 1.2149x; 1.2149x over previous
#include <cuda_runtime.h>

#define NNODES 20000
#define NEDGES 640000
#define DINF   92
#define DPAD   96
#define CF     128
#define NCF    (NNODES*CF)

// ---------------- scratch (device globals; no allocation) ----------------
__device__ __align__(16) float g_X[NCF];
__device__ __align__(16) float g_T[NCF];
__device__ __align__(16) float g_Hb[NCF];
__device__ __align__(16) float g_HHb[NNODES*256];
__device__ __align__(16) float g_AGG[NNODES*256];
__device__ __align__(16) float g_ZOUT[NCF];
__device__ __align__(16) float g_NF[NNODES*DPAD];
__device__ __align__(16) float g_AS[NNODES*2];
__device__ __align__(16) float g_AD[NNODES*2];
__device__ __align__(16) float g_S1[CF];
__device__ __align__(16) float g_S2[CF];
__device__ __align__(16) float g_cs[CF];
__device__ __align__(16) float g_cb[CF];
__device__ int   g_cnt[NNODES];
__device__ int   g_rowptr[NNODES+1];
__device__ int   g_cursor[NNODES];
__device__ int   g_csrc[NEDGES];
__device__ int   g_bsum[32];
__device__ int   g_boff[32];
__device__ int   g_is64;

// ---------------- edge index dtype sniffing ----------------
__global__ void detect_kernel(const void* idx) {
    const int* w = (const int*)idx;
    __shared__ int nz;
    if (threadIdx.x == 0) nz = 0;
    __syncthreads();
    for (int i = threadIdx.x; i < 4096; i += blockDim.x) {
        long long pos = 2LL * i * (NEDGES / 4096) + 1;
        if (pos < 2LL * NEDGES && w[pos] != 0) atomicOr(&nz, 1);
    }
    __syncthreads();
    if (threadIdx.x == 0) g_is64 = (nz == 0) ? 1 : 0;
}
__device__ __forceinline__ int edge_src(const void* p, int e) {
    return g_is64 ? (int)((const long long*)p)[e] : ((const int*)p)[e];
}
__device__ __forceinline__ int edge_dst(const void* p, int e) {
    return g_is64 ? (int)((const long long*)p)[NEDGES + e] : ((const int*)p)[NEDGES + e];
}

// ---------------- CSR build ----------------
__global__ void zero_cnt_kernel() {
    int i = blockIdx.x * blockDim.x + threadIdx.x;
    if (i < NNODES) g_cnt[i] = 0;
}
__global__ void hist_kernel(const void* eidx) {
    int e = blockIdx.x * blockDim.x + threadIdx.x;
    if (e < NEDGES) atomicAdd(&g_cnt[edge_dst(eidx, e)], 1);
}
// 3-phase scan over NNODES counts (20 blocks x 1024)
__global__ void scan1_kernel() {
    __shared__ int ws[32];
    int b = blockIdx.x, tid = threadIdx.x, lane = tid & 31, wid = tid >> 5;
    int i = b * 1024 + tid;
    int v = (i < NNODES) ? g_cnt[i] : 0;
    int x = v;
    #pragma unroll
    for (int o = 1; o < 32; o <<= 1) {
        int y = __shfl_up_sync(0xffffffffu, x, o);
        if (lane >= o) x += y;
    }
    if (lane == 31) ws[wid] = x;
    __syncthreads();
    if (wid == 0) {
        int s = ws[lane];
        #pragma unroll
        for (int o = 1; o < 32; o <<= 1) {
            int y = __shfl_up_sync(0xffffffffu, s, o);
            if (lane >= o) s += y;
        }
        ws[lane] = s;
    }
    __syncthreads();
    int incl = x + (wid > 0 ? ws[wid - 1] : 0);
    if (i < NNODES) g_rowptr[i] = incl - v;   // local exclusive
    if (tid == 1023) g_bsum[b] = incl;
}
__global__ void scan2_kernel() {   // 1 block, 32 threads
    int lane = threadIdx.x;
    int v = (lane < 20) ? g_bsum[lane] : 0;
    int x = v;
    #pragma unroll
    for (int o = 1; o < 32; o <<= 1) {
        int y = __shfl_up_sync(0xffffffffu, x, o);
        if (lane >= o) x += y;
    }
    if (lane < 20) g_boff[lane] = x - v;
    if (lane == 19) g_rowptr[NNODES] = x;
}
__global__ void scan3_kernel() {
    int b = blockIdx.x;
    int i = b * 1024 + threadIdx.x;
    if (i < NNODES) {
        int r = g_rowptr[i] + g_boff[b];
        g_rowptr[i] = r;
        g_cursor[i] = r;
    }
}
__global__ void scatter_kernel(const void* eidx) {
    int e = blockIdx.x * blockDim.x + threadIdx.x;
    if (e < NEDGES) {
        int d = edge_dst(eidx, e);
        int s = edge_src(eidx, e);
        int p = atomicAdd(&g_cursor[d], 1);
        g_csrc[p] = s;
    }
}

// ---------------- pad node features 92 -> 96 ----------------
__global__ void pad_nf_kernel(const float* __restrict__ nf) {
    int i = blockIdx.x * blockDim.x + threadIdx.x;
    if (i < NNODES * DPAD) {
        int n = i / DPAD, c = i - n * DPAD;
        g_NF[i] = (c < DINF) ? nf[n * DINF + c] : 0.f;
    }
}

// ================= main GEMM: Out[M,*] = act(A)@B + bias =================
// Tile 64 rows x 128 cols (blockIdx.y = col block), K-chunk 32, microtile 4x8.
// Optional: per-K affine+relu on A (fused BN+ReLU), per-col stats (BN),
// fused attention dots (head=blockIdx.y -> g_AS/g_AD), fused reparam z.
__global__ void __launch_bounds__(256, 2)
gemm64_kernel(const float* __restrict__ A, int lda, int K, int M,
              const float* __restrict__ B, int ldb,
              const float* __restrict__ bias,
              float* __restrict__ Out, int ldo,
              const float* __restrict__ affs, const float* __restrict__ affb,
              int do_stats,
              const float* __restrict__ atts, const float* __restrict__ attd,
              const float* __restrict__ rp_eps, const float* __restrict__ rp_mu,
              float* __restrict__ rp_z)
{
    __shared__ float As[32][68];   // [k][row], stride 272B (16B aligned)
    __shared__ float Bs[32][128];
    __shared__ float s1[CF], s2[CF];

    const int tid = threadIdx.x;
    const int tx = tid & 15, ty = tid >> 4;
    const int r0 = blockIdx.x * 64;
    const int c0 = blockIdx.y * 128;
    const int nch = K >> 5;

    float acc[4][8];
    #pragma unroll
    for (int i = 0; i < 4; i++)
        #pragma unroll
        for (int j = 0; j < 8; j++) acc[i][j] = 0.f;

    float4 areg[2], breg[4];

    // --- prologue load chunk 0 ---
    {
        const int kt = 0;
        #pragma unroll
        for (int p = 0; p < 2; p++) {
            int idx = p * 256 + tid;
            int row = idx >> 3, kq = idx & 7;
            int grow = r0 + row;
            float4 v = make_float4(0.f, 0.f, 0.f, 0.f);
            if (grow < M) {
                v = *(const float4*)&A[grow * lda + kt + kq * 4];
                if (affs) {
                    int k = kt + kq * 4;
                    v.x = fmaxf(affs[k    ] * v.x + affb[k    ], 0.f);
                    v.y = fmaxf(affs[k + 1] * v.y + affb[k + 1], 0.f);
                    v.z = fmaxf(affs[k + 2] * v.z + affb[k + 2], 0.f);
                    v.w = fmaxf(affs[k + 3] * v.w + affb[k + 3], 0.f);
                }
            }
            areg[p] = v;
        }
        #pragma unroll
        for (int p = 0; p < 4; p++) {
            int idx = p * 256 + tid;
            int kr = idx >> 5, cq = idx & 31;
            breg[p] = *(const float4*)&B[(kt + kr) * ldb + c0 + cq * 4];
        }
        #pragma unroll
        for (int p = 0; p < 2; p++) {
            int idx = p * 256 + tid;
            int row = idx >> 3, kq = idx & 7;
            As[kq * 4 + 0][row] = areg[p].x;
            As[kq * 4 + 1][row] = areg[p].y;
            As[kq * 4 + 2][row] = areg[p].z;
            As[kq * 4 + 3][row] = areg[p].w;
        }
        #pragma unroll
        for (int p = 0; p < 4; p++) {
            int idx = p * 256 + tid;
            int kr = idx >> 5, cq = idx & 31;
            *(float4*)&Bs[kr][cq * 4] = breg[p];
        }
        __syncthreads();
    }

    for (int c = 0; c < nch; c++) {
        if (c + 1 < nch) {
            const int kt = (c + 1) * 32;
            #pragma unroll
            for (int p = 0; p < 2; p++) {
                int idx = p * 256 + tid;
                int row = idx >> 3, kq = idx & 7;
                int grow = r0 + row;
                float4 v = make_float4(0.f, 0.f, 0.f, 0.f);
                if (grow < M) {
                    v = *(const float4*)&A[grow * lda + kt + kq * 4];
                    if (affs) {
                        int k = kt + kq * 4;
                        v.x = fmaxf(affs[k    ] * v.x + affb[k    ], 0.f);
                        v.y = fmaxf(affs[k + 1] * v.y + affb[k + 1], 0.f);
                        v.z = fmaxf(affs[k + 2] * v.z + affb[k + 2], 0.f);
                        v.w = fmaxf(affs[k + 3] * v.w + affb[k + 3], 0.f);
                    }
                }
                areg[p] = v;
            }
            #pragma unroll
            for (int p = 0; p < 4; p++) {
                int idx = p * 256 + tid;
                int kr = idx >> 5, cq = idx & 31;
                breg[p] = *(const float4*)&B[(kt + kr) * ldb + c0 + cq * 4];
            }
        }
        #pragma unroll 8
        for (int kk = 0; kk < 32; kk++) {
            float4 a0 = *(float4*)&As[kk][ty * 4];
            float4 b0 = *(float4*)&Bs[kk][tx * 8];
            float4 b1 = *(float4*)&Bs[kk][tx * 8 + 4];
            float av[4] = {a0.x, a0.y, a0.z, a0.w};
            float bv[8] = {b0.x, b0.y, b0.z, b0.w, b1.x, b1.y, b1.z, b1.w};
            #pragma unroll
            for (int i = 0; i < 4; i++)
                #pragma unroll
                for (int j = 0; j < 8; j++)
                    acc[i][j] += av[i] * bv[j];
        }
        __syncthreads();
        if (c + 1 < nch) {
            #pragma unroll
            for (int p = 0; p < 2; p++) {
                int idx = p * 256 + tid;
                int row = idx >> 3, kq = idx & 7;
                As[kq * 4 + 0][row] = areg[p].x;
                As[kq * 4 + 1][row] = areg[p].y;
                As[kq * 4 + 2][row] = areg[p].z;
                As[kq * 4 + 3][row] = areg[p].w;
            }
            #pragma unroll
            for (int p = 0; p < 4; p++) {
                int idx = p * 256 + tid;
                int kr = idx >> 5, cq = idx & 31;
                *(float4*)&Bs[kr][cq * 4] = breg[p];
            }
            __syncthreads();
        }
    }

    // --- epilogue ---
    float bcol[8];
    #pragma unroll
    for (int j = 0; j < 8; j++)
        bcol[j] = bias ? bias[c0 + tx * 8 + j] : 0.f;

    #pragma unroll
    for (int i = 0; i < 4; i++) {
        int row = r0 + ty * 4 + i;
        if (row < M) {
            float4 o0 = make_float4(acc[i][0] + bcol[0], acc[i][1] + bcol[1],
                                    acc[i][2] + bcol[2], acc[i][3] + bcol[3]);
            float4 o1 = make_float4(acc[i][4] + bcol[4], acc[i][5] + bcol[5],
                                    acc[i][6] + bcol[6], acc[i][7] + bcol[7]);
            *(float4*)&Out[row * ldo + c0 + tx * 8]     = o0;
            *(float4*)&Out[row * ldo + c0 + tx * 8 + 4] = o1;
        }
    }

    if (do_stats) {   // per-column sum/sumsq (c0==0 when used)
        if (tid < CF) { s1[tid] = 0.f; s2[tid] = 0.f; }
        __syncthreads();
        #pragma unroll
        for (int j = 0; j < 8; j++) {
            int cc = tx * 8 + j;
            float sv = 0.f, sq = 0.f;
            #pragma unroll
            for (int i = 0; i < 4; i++) {
                int row = r0 + ty * 4 + i;
                if (row < M) { float v = acc[i][j] + bcol[j]; sv += v; sq += v * v; }
            }
            atomicAdd(&s1[cc], sv);
            atomicAdd(&s2[cc], sq);
        }
        __syncthreads();
        if (tid < CF) { atomicAdd(&g_S1[tid], s1[tid]); atomicAdd(&g_S2[tid], s2[tid]); }
    }

    if (atts) {   // fused a_src/a_dst dots; head = blockIdx.y
        int h = blockIdx.y;
        float avs[8], avd[8];
        #pragma unroll
        for (int j = 0; j < 8; j++) {
            avs[j] = atts[h * CF + tx * 8 + j];
            avd[j] = attd[h * CF + tx * 8 + j];
        }
        #pragma unroll
        for (int i = 0; i < 4; i++) {
            float ss = 0.f, sd = 0.f;
            #pragma unroll
            for (int j = 0; j < 8; j++) {
                float v = acc[i][j];           // no bias on hh
                ss += v * avs[j];
                sd += v * avd[j];
            }
            #pragma unroll
            for (int o = 8; o >= 1; o >>= 1) {
                ss += __shfl_down_sync(0xffffffffu, ss, o, 16);
                sd += __shfl_down_sync(0xffffffffu, sd, o, 16);
            }
            int row = r0 + ty * 4 + i;
            if ((tid & 15) == 0 && row < M) {
                g_AS[row * 2 + h] = ss;
                g_AD[row * 2 + h] = sd;
            }
        }
    }

    if (rp_z) {   // fused z = eps*exp(0.5*logvar)+mu  (c0==0)
        #pragma unroll
        for (int i = 0; i < 4; i++) {
            int row = r0 + ty * 4 + i;
            if (row < M) {
                #pragma unroll
                for (int j = 0; j < 8; j++) {
                    int cc = tx * 8 + j;
                    float lv = acc[i][j] + bcol[j];
                    rp_z[row * CF + cc] = rp_eps[row * CF + cc] * expf(0.5f * lv)
                                        + rp_mu[row * CF + cc];
                }
            }
        }
    }
}

// ---------------- BN ----------------
__global__ void zero_stats_kernel() {
    int i = threadIdx.x;
    if (i < CF) { g_S1[i] = 0.f; g_S2[i] = 0.f; }
}
__global__ void bn_fin_kernel(const float* __restrict__ gam, const float* __restrict__ bet) {
    int c = threadIdx.x;
    if (c < CF) {
        float mu  = g_S1[c] / (float)NNODES;
        float var = g_S2[c] / (float)NNODES - mu * mu;
        float a   = gam[c] * rsqrtf(var + 1e-5f);
        g_cs[c] = a;
        g_cb[c] = bet[c] - mu * a;
    }
}
__global__ void apply_bnrelu_kernel() {
    int i = blockIdx.x * blockDim.x + threadIdx.x;
    if (i < NCF) {
        int c = i & 127;
        g_X[i] = fmaxf(g_cs[c] * g_T[i] + g_cb[c], 0.f);
    }
}

// ---------------- GIN aggregation ----------------
__global__ void gin_agg_kernel() {
    int warp = (blockIdx.x * blockDim.x + threadIdx.x) >> 5;
    int lane = threadIdx.x & 31;
    if (warp >= NNODES) return;
    int n = warp;
    float4 acc = *(const float4*)&g_X[n * CF + lane * 4];
    int beg = g_rowptr[n], end = g_rowptr[n + 1];
    int i = beg;
    for (; i + 1 < end; i += 2) {
        int s0 = g_csrc[i], s1v = g_csrc[i + 1];
        float4 v0 = *(const float4*)&g_X[s0 * CF + lane * 4];
        float4 v1 = *(const float4*)&g_X[s1v * CF + lane * 4];
        acc.x += v0.x + v1.x; acc.y += v0.y + v1.y;
        acc.z += v0.z + v1.z; acc.w += v0.w + v1.w;
    }
    if (i < end) {
        int s0 = g_csrc[i];
        float4 v0 = *(const float4*)&g_X[s0 * CF + lane * 4];
        acc.x += v0.x; acc.y += v0.y; acc.z += v0.z; acc.w += v0.w;
    }
    *(float4*)&g_Hb[n * CF + lane * 4] = acc;
}

__device__ __forceinline__ float lrelu(float x) { return x > 0.f ? x : 0.2f * x; }

// ---------------- GAT aggregation (1 warp per node,head) ----------------
__global__ void gat_agg_kernel(const float* __restrict__ b_gat) {
    int warp = (blockIdx.x * blockDim.x + threadIdx.x) >> 5;
    int lane = threadIdx.x & 31;
    if (warp >= NNODES * 2) return;
    int n = warp >> 1, h = warp & 1;
    float adn   = g_AD[n * 2 + h];
    float lself = lrelu(g_AS[n * 2 + h] + adn);
    int beg = g_rowptr[n], end = g_rowptr[n + 1];

    float m = lself;
    for (int i = beg + lane; i < end; i += 32) {
        int s = g_csrc[i];
        m = fmaxf(m, lrelu(g_AS[s * 2 + h] + adn));
    }
    #pragma unroll
    for (int o = 16; o >= 1; o >>= 1) m = fmaxf(m, __shfl_xor_sync(0xffffffffu, m, o));

    float w = expf(lself - m);
    float ssum = w;
    float4 hv = *(const float4*)&g_HHb[n * 256 + h * CF + lane * 4];
    float4 acc = make_float4(w * hv.x, w * hv.y, w * hv.z, w * hv.w);
    int i = beg;
    for (; i + 1 < end; i += 2) {
        int s0 = g_csrc[i], s1v = g_csrc[i + 1];
        float l0 = lrelu(g_AS[s0 * 2 + h] + adn);
        float l1 = lrelu(g_AS[s1v * 2 + h] + adn);
        float w0 = expf(l0 - m), w1 = expf(l1 - m);
        ssum += w0 + w1;
        float4 v0 = *(const float4*)&g_HHb[s0 * 256 + h * CF + lane * 4];
        float4 v1 = *(const float4*)&g_HHb[s1v * 256 + h * CF + lane * 4];
        acc.x += w0 * v0.x + w1 * v1.x;
        acc.y += w0 * v0.y + w1 * v1.y;
        acc.z += w0 * v0.z + w1 * v1.z;
        acc.w += w0 * v0.w + w1 * v1.w;
    }
    if (i < end) {
        int s0 = g_csrc[i];
        float l0 = lrelu(g_AS[s0 * 2 + h] + adn);
        float w0 = expf(l0 - m);
        ssum += w0;
        float4 v0 = *(const float4*)&g_HHb[s0 * 256 + h * CF + lane * 4];
        acc.x += w0 * v0.x; acc.y += w0 * v0.y; acc.z += w0 * v0.z; acc.w += w0 * v0.w;
    }
    float inv = 1.f / ssum;
    float4 bg = *(const float4*)&b_gat[h * CF + lane * 4];
    float4 o4 = make_float4(acc.x * inv + bg.x, acc.y * inv + bg.y,
                            acc.z * inv + bg.z, acc.w * inv + bg.w);
    *(float4*)&g_AGG[n * 256 + h * CF + lane * 4] = o4;
}

// ---------------- host orchestration ----------------
extern "C" void kernel_launch(void* const* d_in, const int* in_sizes, int n_in,
                              void* d_out, int out_size) {
    const float* nf     = (const float*)d_in[0];
    const void*  eidx   =               d_in[1];
    const float* eps    = (const float*)d_in[2];
    const float* W_emb  = (const float*)d_in[3];
    const float* b_emb  = (const float*)d_in[4];
    const float* g_emb  = (const float*)d_in[5];
    const float* be_emb = (const float*)d_in[6];
    const float* W1     = (const float*)d_in[7];
    const float* b1     = (const float*)d_in[8];
    const float* g1     = (const float*)d_in[9];
    const float* be1    = (const float*)d_in[10];
    const float* W2     = (const float*)d_in[11];
    const float* b2     = (const float*)d_in[12];
    const float* W_mu   = (const float*)d_in[13];
    const float* b_mu   = (const float*)d_in[14];
    const float* W_var  = (const float*)d_in[15];
    const float* b_var  = (const float*)d_in[16];
    const float* W_gat  = (const float*)d_in[17];
    const float* att_s  = (const float*)d_in[18];
    const float* att_d  = (const float*)d_in[19];
    const float* b_gat  = (const float*)d_in[20];
    const float* W_dec  = (const float*)d_in[21];
    const float* b_dec  = (const float*)d_in[22];
    float* out = (float*)d_out;

    float *X, *T, *Hb, *HHp, *AGG, *ZOUT, *CS, *CB, *NF;
    cudaGetSymbolAddress((void**)&X,    g_X);
    cudaGetSymbolAddress((void**)&T,    g_T);
    cudaGetSymbolAddress((void**)&Hb,   g_Hb);
    cudaGetSymbolAddress((void**)&HHp,  g_HHb);
    cudaGetSymbolAddress((void**)&AGG,  g_AGG);
    cudaGetSymbolAddress((void**)&ZOUT, g_ZOUT);
    cudaGetSymbolAddress((void**)&CS,   g_cs);
    cudaGetSymbolAddress((void**)&CB,   g_cb);
    cudaGetSymbolAddress((void**)&NF,   g_NF);

    const int GX = (NNODES + 63) / 64;   // 313
    dim3 grid1(GX, 1), grid2(GX, 2);
    const int EB = (NEDGES + 255) / 256;
    const int NB = (NNODES + 255) / 256;
    const int WARP_N  = (NNODES * 32 + 255) / 256;
    const int WARP_2N = (NNODES * 2 * 32 + 255) / 256;
    const int ELB = (NCF + 255) / 256;
    const int PB  = (NNODES * DPAD + 255) / 256;

    // CSR build
    detect_kernel<<<1, 256>>>(eidx);
    zero_cnt_kernel<<<NB, 256>>>();
    hist_kernel<<<EB, 256>>>(eidx);
    scan1_kernel<<<20, 1024>>>();
    scan2_kernel<<<1, 32>>>();
    scan3_kernel<<<20, 1024>>>();
    scatter_kernel<<<EB, 256>>>(eidx);

    // atom embedding
    pad_nf_kernel<<<PB, 256>>>(nf);
    zero_stats_kernel<<<1, 128>>>();
    gemm64_kernel<<<grid1, 256>>>(NF, DPAD, DPAD, NNODES, W_emb, CF, b_emb, T, CF,
                                  nullptr, nullptr, 1, nullptr, nullptr,
                                  nullptr, nullptr, nullptr);
    bn_fin_kernel<<<1, 128>>>(g_emb, be_emb);
    apply_bnrelu_kernel<<<ELB, 256>>>();

    // GIN encoder x2 (shared weights)
    for (int l = 0; l < 2; l++) {
        gin_agg_kernel<<<WARP_N, 256>>>();
        zero_stats_kernel<<<1, 128>>>();
        gemm64_kernel<<<grid1, 256>>>(Hb, CF, CF, NNODES, W1, CF, b1, T, CF,
                                      nullptr, nullptr, 1, nullptr, nullptr,
                                      nullptr, nullptr, nullptr);
        bn_fin_kernel<<<1, 128>>>(g1, be1);
        gemm64_kernel<<<grid1, 256>>>(T, CF, CF, NNODES, W2, CF, b2, X, CF,
                                      CS, CB, 0, nullptr, nullptr,
                                      nullptr, nullptr, nullptr);
    }

    // VAE heads: mu, then logvar with fused z
    gemm64_kernel<<<grid1, 256>>>(X, CF, CF, NNODES, W_mu, CF, b_mu, out + 2 * NCF, CF,
                                  nullptr, nullptr, 0, nullptr, nullptr,
                                  nullptr, nullptr, nullptr);
    gemm64_kernel<<<grid1, 256>>>(X, CF, CF, NNODES, W_var, CF, b_var, out + 3 * NCF, CF,
                                  nullptr, nullptr, 0, nullptr, nullptr,
                                  eps, out + 2 * NCF, out);

    // GAT decoder x2 (shared weights)
    for (int l = 0; l < 2; l++) {
        const float* zcur = (l == 0) ? out : ZOUT;
        float* zdst       = (l == 0) ? ZOUT : out + NCF;
        gemm64_kernel<<<grid2, 256>>>(zcur, CF, CF, NNODES, W_gat, 256, nullptr, HHp, 256,
                                      nullptr, nullptr, 0, att_s, att_d,
                                      nullptr, nullptr, nullptr);
        gat_agg_kernel<<<WARP_2N, 256>>>(b_gat);
        gemm64_kernel<<<grid1, 256>>>(AGG, 256, 256, NNODES, W_dec, CF, b_dec, zdst, CF,
                                      nullptr, nullptr, 0, nullptr, nullptr,
                                      nullptr, nullptr, nullptr);
    }
    (void)in_sizes; (void)n_in; (void)out_size;
}

// round 6
// speedup vs baseline: 1.9769x; 1.6272x over previous
#include <cuda_runtime.h>
#include <cuda_bf16.h>
#include <cstdint>

#define NNODES 20000
#define NEDGES 640000
#define DINF   92
#define DPAD   128
#define CF     128
#define NCF    (NNODES*CF)

// ---------------- scratch (device globals; no allocation) ----------------
__device__ __align__(16) float g_X[NCF];
__device__ __align__(16) float g_T[NCF];
__device__ __align__(16) float g_Hb[NCF];
__device__ __align__(16) float g_HHb[NNODES*256];
__device__ __align__(16) float g_AGG[NNODES*256];
__device__ __align__(16) float g_ZOUT[NCF];
__device__ __align__(16) float g_NF[NNODES*DPAD];
__device__ __align__(16) uint32_t g_BHI[98304];   // packed bf16-pair weight images
__device__ __align__(16) uint32_t g_BLO[98304];
__device__ __align__(16) float g_AS[NNODES*2];
__device__ __align__(16) float g_AD[NNODES*2];
__device__ __align__(16) float g_S1[CF];
__device__ __align__(16) float g_S2[CF];
__device__ __align__(16) float g_cs[CF];
__device__ __align__(16) float g_cb[CF];
__device__ int   g_cnt[NNODES];
__device__ int   g_rowptr[NNODES+1];
__device__ int   g_cursor[NNODES];
__device__ int   g_csrc[NEDGES];
__device__ int   g_bsum[32];
__device__ int   g_boff[32];
__device__ int   g_is64;

// ---------------- bf16 hi/lo split + pack ----------------
__device__ __forceinline__ void split_pack(float e0, float e1,
                                           uint32_t& hp, uint32_t& lp) {
    unsigned short h0 = __bfloat16_as_ushort(__float2bfloat16_rn(e0));
    unsigned short h1 = __bfloat16_as_ushort(__float2bfloat16_rn(e1));
    float f0 = __uint_as_float((uint32_t)h0 << 16);
    float f1 = __uint_as_float((uint32_t)h1 << 16);
    unsigned short l0 = __bfloat16_as_ushort(__float2bfloat16_rn(e0 - f0));
    unsigned short l1 = __bfloat16_as_ushort(__float2bfloat16_rn(e1 - f1));
    hp = (uint32_t)h0 | ((uint32_t)h1 << 16);
    lp = (uint32_t)l0 | ((uint32_t)l1 << 16);
}

__device__ __forceinline__ void mma16816(float& d0, float& d1, float& d2, float& d3,
                                         uint32_t a0, uint32_t a1, uint32_t a2, uint32_t a3,
                                         uint32_t b0, uint32_t b1) {
    asm volatile(
        "mma.sync.aligned.m16n8k16.row.col.f32.bf16.bf16.f32 "
        "{%0,%1,%2,%3}, {%4,%5,%6,%7}, {%8,%9}, {%0,%1,%2,%3};"
        : "+f"(d0), "+f"(d1), "+f"(d2), "+f"(d3)
        : "r"(a0), "r"(a1), "r"(a2), "r"(a3), "r"(b0), "r"(b1));
}

// ---------------- edge index dtype sniffing ----------------
__global__ void detect_kernel(const void* idx) {
    const int* w = (const int*)idx;
    __shared__ int nz;
    if (threadIdx.x == 0) nz = 0;
    __syncthreads();
    for (int i = threadIdx.x; i < 4096; i += blockDim.x) {
        long long pos = 2LL * i * (NEDGES / 4096) + 1;
        if (pos < 2LL * NEDGES && w[pos] != 0) atomicOr(&nz, 1);
    }
    __syncthreads();
    if (threadIdx.x == 0) g_is64 = (nz == 0) ? 1 : 0;
}
__device__ __forceinline__ int edge_src(const void* p, int e) {
    return g_is64 ? (int)((const long long*)p)[e] : ((const int*)p)[e];
}
__device__ __forceinline__ int edge_dst(const void* p, int e) {
    return g_is64 ? (int)((const long long*)p)[NEDGES + e] : ((const int*)p)[NEDGES + e];
}

// ---------------- CSR build ----------------
__global__ void zero_cnt_kernel() {
    int i = blockIdx.x * blockDim.x + threadIdx.x;
    if (i < NNODES) g_cnt[i] = 0;
}
__global__ void hist_kernel(const void* eidx) {
    int e = blockIdx.x * blockDim.x + threadIdx.x;
    if (e < NEDGES) atomicAdd(&g_cnt[edge_dst(eidx, e)], 1);
}
__global__ void scan1_kernel() {
    __shared__ int ws[32];
    int b = blockIdx.x, tid = threadIdx.x, lane = tid & 31, wid = tid >> 5;
    int i = b * 1024 + tid;
    int v = (i < NNODES) ? g_cnt[i] : 0;
    int x = v;
    #pragma unroll
    for (int o = 1; o < 32; o <<= 1) {
        int y = __shfl_up_sync(0xffffffffu, x, o);
        if (lane >= o) x += y;
    }
    if (lane == 31) ws[wid] = x;
    __syncthreads();
    if (wid == 0) {
        int s = ws[lane];
        #pragma unroll
        for (int o = 1; o < 32; o <<= 1) {
            int y = __shfl_up_sync(0xffffffffu, s, o);
            if (lane >= o) s += y;
        }
        ws[lane] = s;
    }
    __syncthreads();
    int incl = x + (wid > 0 ? ws[wid - 1] : 0);
    if (i < NNODES) g_rowptr[i] = incl - v;
    if (tid == 1023) g_bsum[b] = incl;
}
__global__ void scan2_kernel() {
    int lane = threadIdx.x;
    int v = (lane < 20) ? g_bsum[lane] : 0;
    int x = v;
    #pragma unroll
    for (int o = 1; o < 32; o <<= 1) {
        int y = __shfl_up_sync(0xffffffffu, x, o);
        if (lane >= o) x += y;
    }
    if (lane < 20) g_boff[lane] = x - v;
    if (lane == 19) g_rowptr[NNODES] = x;
}
__global__ void scan3_kernel() {
    int b = blockIdx.x;
    int i = b * 1024 + threadIdx.x;
    if (i < NNODES) {
        int r = g_rowptr[i] + g_boff[b];
        g_rowptr[i] = r;
        g_cursor[i] = r;
    }
}
__global__ void scatter_kernel(const void* eidx) {
    int e = blockIdx.x * blockDim.x + threadIdx.x;
    if (e < NEDGES) {
        int d = edge_dst(eidx, e);
        int s = edge_src(eidx, e);
        int p = atomicAdd(&g_cursor[d], 1);
        g_csrc[p] = s;
    }
}

// ---------------- pad node features 92 -> 128 ----------------
__global__ void pad_nf_kernel(const float* __restrict__ nf) {
    int i = blockIdx.x * blockDim.x + threadIdx.x;
    if (i < NNODES * DPAD) {
        int n = i >> 7, c = i & 127;
        g_NF[i] = (c < DINF) ? nf[n * DINF + c] : 0.f;
    }
}

// ---------------- pack weights: W[K,N] -> bf16 hi/lo pair images ----------------
// image layout: [nb][nr 128][kp Kpad/2] u32 pairs (k-pairs contiguous)
__global__ void pack_b_kernel(const float* __restrict__ W, int Kreal, int Kpad, int N,
                              uint32_t base) {
    int idx = blockIdx.x * blockDim.x + threadIdx.x;
    int pairs = Kpad >> 1;
    int tot = N * pairs;
    if (idx >= tot) return;
    int n = idx / pairs, kp = idx - n * pairs;
    int nb = n >> 7, nr = n & 127;
    int k0 = 2 * kp;
    float v0 = (k0     < Kreal) ? W[k0 * N + n]       : 0.f;
    float v1 = (k0 + 1 < Kreal) ? W[(k0 + 1) * N + n] : 0.f;
    uint32_t hp, lp;
    split_pack(v0, v1, hp, lp);
    uint32_t off = base + (uint32_t)nb * 128u * pairs + (uint32_t)nr * pairs + kp;
    g_BHI[off] = hp;
    g_BLO[off] = lp;
}

// ================= bf16 3-product mma.sync GEMM =================
// Out[M, N] = act(A)[M,K] @ W[K,N] + bias. Block tile 128x128 (blockIdx.y = nb),
// warp tile 64x32. 3 products: Ahi*Bhi + Ahi*Blo + Alo*Bhi.
// Fusions: affine+relu on A load, BN stats, attention dots (head=nb), reparam z.
__global__ void __launch_bounds__(256, 2)
mm_gemm(const float* __restrict__ A, int lda, int Kc /* K/32 */, int M,
        uint32_t bbase,
        const float* __restrict__ bias,
        float* __restrict__ Out, int ldo,
        const float* __restrict__ affs, const float* __restrict__ affb,
        int do_stats,
        const float* __restrict__ atts, const float* __restrict__ attd,
        const float* __restrict__ rp_eps, const float* __restrict__ rp_mu,
        float* __restrict__ rp_z)
{
    __shared__ uint32_t AHI[128 * 20], ALO[128 * 20];
    __shared__ uint32_t BHI[128 * 20], BLO[128 * 20];
    __shared__ float    RED1[128], RED2[128];

    const int tid = threadIdx.x, wid = tid >> 5, lane = tid & 31;
    const int g = lane >> 2, tc = lane & 3;
    const int wm = wid >> 2, wn = wid & 3;          // warp 2x4 grid
    const int r0 = blockIdx.x * 128;
    const int nb = blockIdx.y;
    const int c0 = nb * 128;
    const int pairsK = Kc * 16;
    const uint32_t bimg = bbase + (uint32_t)nb * 128u * pairsK;

    float acc[4][4][4];
    #pragma unroll
    for (int mt = 0; mt < 4; mt++)
        #pragma unroll
        for (int nt = 0; nt < 4; nt++)
            #pragma unroll
            for (int q = 0; q < 4; q++) acc[mt][nt][q] = 0.f;

    for (int c = 0; c < Kc; c++) {
        __syncthreads();   // previous mma done before overwrite
        // ---- stage A: 128 rows x 16 pairs
        #pragma unroll
        for (int i = 0; i < 8; i++) {
            int idx = i * 256 + tid;
            int row = idx >> 4, p = idx & 15;
            int grow = r0 + row;
            float2 v = make_float2(0.f, 0.f);
            if (grow < M) {
                v = *(const float2*)&A[(size_t)grow * lda + c * 32 + p * 2];
                if (affs) {
                    int k = c * 32 + p * 2;
                    v.x = fmaxf(affs[k    ] * v.x + affb[k    ], 0.f);
                    v.y = fmaxf(affs[k + 1] * v.y + affb[k + 1], 0.f);
                }
            }
            uint32_t hp, lp;
            split_pack(v.x, v.y, hp, lp);
            AHI[row * 20 + p] = hp;
            ALO[row * 20 + p] = lp;
        }
        // ---- stage B: 128 n-rows x 16 pairs (pre-packed)
        #pragma unroll
        for (int i = 0; i < 8; i++) {
            int idx = i * 256 + tid;
            int n = idx >> 4, p = idx & 15;
            uint32_t src = bimg + (uint32_t)n * pairsK + c * 16 + p;
            BHI[n * 20 + p] = g_BHI[src];
            BLO[n * 20 + p] = g_BLO[src];
        }
        __syncthreads();

        // ---- 3 products x 2 k16-steps x 16 mma
        #pragma unroll
        for (int prod = 0; prod < 3; prod++) {
            const uint32_t* Ab = (prod == 2) ? ALO : AHI;
            const uint32_t* Bb = (prod == 1) ? BLO : BHI;
            #pragma unroll
            for (int ks = 0; ks < 2; ks++) {
                uint32_t af[4][4], bf[4][2];
                #pragma unroll
                for (int mt = 0; mt < 4; mt++) {
                    int rbase = (wm * 64 + mt * 16 + g) * 20 + ks * 8 + tc;
                    af[mt][0] = Ab[rbase];
                    af[mt][1] = Ab[rbase + 8 * 20];
                    af[mt][2] = Ab[rbase + 4];
                    af[mt][3] = Ab[rbase + 8 * 20 + 4];
                }
                #pragma unroll
                for (int nt = 0; nt < 4; nt++) {
                    int nbase = (wn * 32 + nt * 8 + g) * 20 + ks * 8 + tc;
                    bf[nt][0] = Bb[nbase];
                    bf[nt][1] = Bb[nbase + 4];
                }
                #pragma unroll
                for (int mt = 0; mt < 4; mt++)
                    #pragma unroll
                    for (int nt = 0; nt < 4; nt++)
                        mma16816(acc[mt][nt][0], acc[mt][nt][1],
                                 acc[mt][nt][2], acc[mt][nt][3],
                                 af[mt][0], af[mt][1], af[mt][2], af[mt][3],
                                 bf[nt][0], bf[nt][1]);
            }
        }
    }

    // ---- epilogue: thread elems rows wm*64+mt*16+g(+8), cols wn*32+nt*8+2tc(+1)
    float bc[4][2];
    #pragma unroll
    for (int nt = 0; nt < 4; nt++) {
        int cc = c0 + wn * 32 + nt * 8 + tc * 2;
        bc[nt][0] = bias ? bias[cc]     : 0.f;
        bc[nt][1] = bias ? bias[cc + 1] : 0.f;
    }

    #pragma unroll
    for (int mt = 0; mt < 4; mt++) {
        int row0 = r0 + wm * 64 + mt * 16 + g;
        int row1 = row0 + 8;
        #pragma unroll
        for (int nt = 0; nt < 4; nt++) {
            int cc = c0 + wn * 32 + nt * 8 + tc * 2;
            if (row0 < M) {
                float2 o = make_float2(acc[mt][nt][0] + bc[nt][0],
                                       acc[mt][nt][1] + bc[nt][1]);
                *(float2*)&Out[(size_t)row0 * ldo + cc] = o;
            }
            if (row1 < M) {
                float2 o = make_float2(acc[mt][nt][2] + bc[nt][0],
                                       acc[mt][nt][3] + bc[nt][1]);
                *(float2*)&Out[(size_t)row1 * ldo + cc] = o;
            }
        }
    }

    if (do_stats) {
        if (tid < CF) { RED1[tid] = 0.f; RED2[tid] = 0.f; }
        __syncthreads();
        #pragma unroll
        for (int nt = 0; nt < 4; nt++) {
            int ccl = wn * 32 + nt * 8 + tc * 2;
            float s0 = 0.f, q0 = 0.f, s1 = 0.f, q1 = 0.f;
            #pragma unroll
            for (int mt = 0; mt < 4; mt++) {
                int row0 = r0 + wm * 64 + mt * 16 + g;
                if (row0 < M) {
                    float v0 = acc[mt][nt][0] + bc[nt][0];
                    float v1 = acc[mt][nt][1] + bc[nt][1];
                    s0 += v0; q0 += v0 * v0; s1 += v1; q1 += v1 * v1;
                }
                if (row0 + 8 < M) {
                    float v0 = acc[mt][nt][2] + bc[nt][0];
                    float v1 = acc[mt][nt][3] + bc[nt][1];
                    s0 += v0; q0 += v0 * v0; s1 += v1; q1 += v1 * v1;
                }
            }
            atomicAdd(&RED1[ccl], s0); atomicAdd(&RED2[ccl], q0);
            atomicAdd(&RED1[ccl + 1], s1); atomicAdd(&RED2[ccl + 1], q1);
        }
        __syncthreads();
        if (tid < CF) { atomicAdd(&g_S1[tid], RED1[tid]); atomicAdd(&g_S2[tid], RED2[tid]); }
    }

    if (atts) {   // per-row dots with att vecs (head = nb); no bias on this GEMM
        if (tid < 128) { RED1[tid] = 0.f; RED2[tid] = 0.f; }
        __syncthreads();
        float avs[4][2], avd[4][2];
        #pragma unroll
        for (int nt = 0; nt < 4; nt++) {
            int cc = wn * 32 + nt * 8 + tc * 2;
            avs[nt][0] = atts[nb * CF + cc]; avs[nt][1] = atts[nb * CF + cc + 1];
            avd[nt][0] = attd[nb * CF + cc]; avd[nt][1] = attd[nb * CF + cc + 1];
        }
        #pragma unroll
        for (int mt = 0; mt < 4; mt++) {
            float ss0 = 0.f, sd0 = 0.f, ss1 = 0.f, sd1 = 0.f;
            #pragma unroll
            for (int nt = 0; nt < 4; nt++) {
                ss0 += acc[mt][nt][0] * avs[nt][0] + acc[mt][nt][1] * avs[nt][1];
                sd0 += acc[mt][nt][0] * avd[nt][0] + acc[mt][nt][1] * avd[nt][1];
                ss1 += acc[mt][nt][2] * avs[nt][0] + acc[mt][nt][3] * avs[nt][1];
                sd1 += acc[mt][nt][2] * avd[nt][0] + acc[mt][nt][3] * avd[nt][1];
            }
            int rl = wm * 64 + mt * 16 + g;
            atomicAdd(&RED1[rl], ss0);     atomicAdd(&RED2[rl], sd0);
            atomicAdd(&RED1[rl + 8], ss1); atomicAdd(&RED2[rl + 8], sd1);
        }
        __syncthreads();
        if (tid < 128 && r0 + tid < M) {
            g_AS[(r0 + tid) * 2 + nb] = RED1[tid];
            g_AD[(r0 + tid) * 2 + nb] = RED2[tid];
        }
    }

    if (rp_z) {   // z = eps*exp(0.5*logvar)+mu (c0 == 0, single nb)
        #pragma unroll
        for (int mt = 0; mt < 4; mt++) {
            int row0 = r0 + wm * 64 + mt * 16 + g;
            int row1 = row0 + 8;
            #pragma unroll
            for (int nt = 0; nt < 4; nt++) {
                int cc = wn * 32 + nt * 8 + tc * 2;
                if (row0 < M) {
                    size_t b = (size_t)row0 * CF + cc;
                    rp_z[b]     = rp_eps[b]     * expf(0.5f * (acc[mt][nt][0] + bc[nt][0])) + rp_mu[b];
                    rp_z[b + 1] = rp_eps[b + 1] * expf(0.5f * (acc[mt][nt][1] + bc[nt][1])) + rp_mu[b + 1];
                }
                if (row1 < M) {
                    size_t b = (size_t)row1 * CF + cc;
                    rp_z[b]     = rp_eps[b]     * expf(0.5f * (acc[mt][nt][2] + bc[nt][0])) + rp_mu[b];
                    rp_z[b + 1] = rp_eps[b + 1] * expf(0.5f * (acc[mt][nt][3] + bc[nt][1])) + rp_mu[b + 1];
                }
            }
        }
    }
}

// ---------------- BN ----------------
__global__ void zero_stats_kernel() {
    int i = threadIdx.x;
    if (i < CF) { g_S1[i] = 0.f; g_S2[i] = 0.f; }
}
__global__ void bn_fin_kernel(const float* __restrict__ gam, const float* __restrict__ bet) {
    int c = threadIdx.x;
    if (c < CF) {
        float mu  = g_S1[c] / (float)NNODES;
        float var = g_S2[c] / (float)NNODES - mu * mu;
        float a   = gam[c] * rsqrtf(var + 1e-5f);
        g_cs[c] = a;
        g_cb[c] = bet[c] - mu * a;
    }
}
__global__ void apply_bnrelu_kernel() {
    int i = blockIdx.x * blockDim.x + threadIdx.x;
    if (i < NCF) {
        int c = i & 127;
        g_X[i] = fmaxf(g_cs[c] * g_T[i] + g_cb[c], 0.f);
    }
}

// ---------------- GIN aggregation ----------------
__global__ void gin_agg_kernel() {
    int warp = (blockIdx.x * blockDim.x + threadIdx.x) >> 5;
    int lane = threadIdx.x & 31;
    if (warp >= NNODES) return;
    int n = warp;
    float4 acc = *(const float4*)&g_X[n * CF + lane * 4];
    int beg = g_rowptr[n], end = g_rowptr[n + 1];
    int i = beg;
    for (; i + 1 < end; i += 2) {
        int s0 = g_csrc[i], s1v = g_csrc[i + 1];
        float4 v0 = *(const float4*)&g_X[s0 * CF + lane * 4];
        float4 v1 = *(const float4*)&g_X[s1v * CF + lane * 4];
        acc.x += v0.x + v1.x; acc.y += v0.y + v1.y;
        acc.z += v0.z + v1.z; acc.w += v0.w + v1.w;
    }
    if (i < end) {
        int s0 = g_csrc[i];
        float4 v0 = *(const float4*)&g_X[s0 * CF + lane * 4];
        acc.x += v0.x; acc.y += v0.y; acc.z += v0.z; acc.w += v0.w;
    }
    *(float4*)&g_Hb[n * CF + lane * 4] = acc;
}

__device__ __forceinline__ float lrelu(float x) { return x > 0.f ? x : 0.2f * x; }

// ---------------- GAT aggregation (1 warp per node,head) ----------------
__global__ void gat_agg_kernel(const float* __restrict__ b_gat) {
    int warp = (blockIdx.x * blockDim.x + threadIdx.x) >> 5;
    int lane = threadIdx.x & 31;
    if (warp >= NNODES * 2) return;
    int n = warp >> 1, h = warp & 1;
    float adn   = g_AD[n * 2 + h];
    float lself = lrelu(g_AS[n * 2 + h] + adn);
    int beg = g_rowptr[n], end = g_rowptr[n + 1];

    float m = lself;
    for (int i = beg + lane; i < end; i += 32) {
        int s = g_csrc[i];
        m = fmaxf(m, lrelu(g_AS[s * 2 + h] + adn));
    }
    #pragma unroll
    for (int o = 16; o >= 1; o >>= 1) m = fmaxf(m, __shfl_xor_sync(0xffffffffu, m, o));

    float w = expf(lself - m);
    float ssum = w;
    float4 hv = *(const float4*)&g_HHb[n * 256 + h * CF + lane * 4];
    float4 acc = make_float4(w * hv.x, w * hv.y, w * hv.z, w * hv.w);
    int i = beg;
    for (; i + 1 < end; i += 2) {
        int s0 = g_csrc[i], s1v = g_csrc[i + 1];
        float l0 = lrelu(g_AS[s0 * 2 + h] + adn);
        float l1 = lrelu(g_AS[s1v * 2 + h] + adn);
        float w0 = expf(l0 - m), w1 = expf(l1 - m);
        ssum += w0 + w1;
        float4 v0 = *(const float4*)&g_HHb[s0 * 256 + h * CF + lane * 4];
        float4 v1 = *(const float4*)&g_HHb[s1v * 256 + h * CF + lane * 4];
        acc.x += w0 * v0.x + w1 * v1.x;
        acc.y += w0 * v0.y + w1 * v1.y;
        acc.z += w0 * v0.z + w1 * v1.z;
        acc.w += w0 * v0.w + w1 * v1.w;
    }
    if (i < end) {
        int s0 = g_csrc[i];
        float l0 = lrelu(g_AS[s0 * 2 + h] + adn);
        float w0 = expf(l0 - m);
        ssum += w0;
        float4 v0 = *(const float4*)&g_HHb[s0 * 256 + h * CF + lane * 4];
        acc.x += w0 * v0.x; acc.y += w0 * v0.y; acc.z += w0 * v0.z; acc.w += w0 * v0.w;
    }
    float inv = 1.f / ssum;
    float4 bg = *(const float4*)&b_gat[h * CF + lane * 4];
    float4 o4 = make_float4(acc.x * inv + bg.x, acc.y * inv + bg.y,
                            acc.z * inv + bg.z, acc.w * inv + bg.w);
    *(float4*)&g_AGG[n * 256 + h * CF + lane * 4] = o4;
}

// ---------------- host orchestration ----------------
extern "C" void kernel_launch(void* const* d_in, const int* in_sizes, int n_in,
                              void* d_out, int out_size) {
    const float* nf     = (const float*)d_in[0];
    const void*  eidx   =               d_in[1];
    const float* eps    = (const float*)d_in[2];
    const float* b_emb  = (const float*)d_in[4];
    const float* g_embp = (const float*)d_in[5];
    const float* be_emb = (const float*)d_in[6];
    const float* b1     = (const float*)d_in[8];
    const float* g1     = (const float*)d_in[9];
    const float* be1    = (const float*)d_in[10];
    const float* b2     = (const float*)d_in[12];
    const float* b_mu   = (const float*)d_in[14];
    const float* b_var  = (const float*)d_in[16];
    const float* att_s  = (const float*)d_in[18];
    const float* att_d  = (const float*)d_in[19];
    const float* b_gat  = (const float*)d_in[20];
    const float* b_dec  = (const float*)d_in[22];
    const float* W_emb  = (const float*)d_in[3];
    const float* W1     = (const float*)d_in[7];
    const float* W2     = (const float*)d_in[11];
    const float* W_mu   = (const float*)d_in[13];
    const float* W_var  = (const float*)d_in[15];
    const float* W_gat  = (const float*)d_in[17];
    const float* W_dec  = (const float*)d_in[21];
    float* out = (float*)d_out;

    float *X, *T, *Hb, *HHp, *AGG, *ZOUT, *CS, *CB, *NF;
    cudaGetSymbolAddress((void**)&X,    g_X);
    cudaGetSymbolAddress((void**)&T,    g_T);
    cudaGetSymbolAddress((void**)&Hb,   g_Hb);
    cudaGetSymbolAddress((void**)&HHp,  g_HHb);
    cudaGetSymbolAddress((void**)&AGG,  g_AGG);
    cudaGetSymbolAddress((void**)&ZOUT, g_ZOUT);
    cudaGetSymbolAddress((void**)&CS,   g_cs);
    cudaGetSymbolAddress((void**)&CB,   g_cb);
    cudaGetSymbolAddress((void**)&NF,   g_NF);

    const int GX = (NNODES + 127) / 128;   // 157
    dim3 grid1(GX, 1), grid2(GX, 2);
    const int EB = (NEDGES + 255) / 256;
    const int NB = (NNODES + 255) / 256;
    const int WARP_N  = (NNODES * 32 + 255) / 256;
    const int WARP_2N = (NNODES * 2 * 32 + 255) / 256;
    const int ELB = (NCF + 255) / 256;
    const int PB  = (NNODES * DPAD + 255) / 256;

    // B image bases (u32 pair offsets)
    const uint32_t O_EMB = 0;       // N=128, Kpad=128 -> 8192
    const uint32_t O_W1  = 8192;
    const uint32_t O_W2  = 16384;
    const uint32_t O_MU  = 24576;
    const uint32_t O_VAR = 32768;
    const uint32_t O_GAT = 40960;   // N=256 -> 16384
    const uint32_t O_DEC = 57344;   // Kpad=256, N=128 -> 16384

    // weight packing (once per launch; tiny)
    pack_b_kernel<<<(128*64 + 255) / 256, 256>>>(W_emb, DINF, 128, 128, O_EMB);
    pack_b_kernel<<<(128*64 + 255) / 256, 256>>>(W1,    128, 128, 128, O_W1);
    pack_b_kernel<<<(128*64 + 255) / 256, 256>>>(W2,    128, 128, 128, O_W2);
    pack_b_kernel<<<(128*64 + 255) / 256, 256>>>(W_mu,  128, 128, 128, O_MU);
    pack_b_kernel<<<(128*64 + 255) / 256, 256>>>(W_var, 128, 128, 128, O_VAR);
    pack_b_kernel<<<(256*64 + 255) / 256, 256>>>(W_gat, 128, 128, 256, O_GAT);
    pack_b_kernel<<<(128*128 + 255) / 256, 256>>>(W_dec, 256, 256, 128, O_DEC);

    // CSR build
    detect_kernel<<<1, 256>>>(eidx);
    zero_cnt_kernel<<<NB, 256>>>();
    hist_kernel<<<EB, 256>>>(eidx);
    scan1_kernel<<<20, 1024>>>();
    scan2_kernel<<<1, 32>>>();
    scan3_kernel<<<20, 1024>>>();
    scatter_kernel<<<EB, 256>>>(eidx);

    // atom embedding
    pad_nf_kernel<<<PB, 256>>>(nf);
    zero_stats_kernel<<<1, 128>>>();
    mm_gemm<<<grid1, 256>>>(NF, DPAD, 4, NNODES, O_EMB, b_emb, T, CF,
                            nullptr, nullptr, 1, nullptr, nullptr,
                            nullptr, nullptr, nullptr);
    bn_fin_kernel<<<1, 128>>>(g_embp, be_emb);
    apply_bnrelu_kernel<<<ELB, 256>>>();

    // GIN encoder x2 (shared weights)
    for (int l = 0; l < 2; l++) {
        gin_agg_kernel<<<WARP_N, 256>>>();
        zero_stats_kernel<<<1, 128>>>();
        mm_gemm<<<grid1, 256>>>(Hb, CF, 4, NNODES, O_W1, b1, T, CF,
                                nullptr, nullptr, 1, nullptr, nullptr,
                                nullptr, nullptr, nullptr);
        bn_fin_kernel<<<1, 128>>>(g1, be1);
        mm_gemm<<<grid1, 256>>>(T, CF, 4, NNODES, O_W2, b2, X, CF,
                                CS, CB, 0, nullptr, nullptr,
                                nullptr, nullptr, nullptr);
    }

    // VAE heads: mu, then logvar with fused z
    mm_gemm<<<grid1, 256>>>(X, CF, 4, NNODES, O_MU, b_mu, out + 2 * NCF, CF,
                            nullptr, nullptr, 0, nullptr, nullptr,
                            nullptr, nullptr, nullptr);
    mm_gemm<<<grid1, 256>>>(X, CF, 4, NNODES, O_VAR, b_var, out + 3 * NCF, CF,
                            nullptr, nullptr, 0, nullptr, nullptr,
                            eps, out + 2 * NCF, out);

    // GAT decoder x2 (shared weights)
    for (int l = 0; l < 2; l++) {
        const float* zcur = (l == 0) ? out : ZOUT;
        float* zdst       = (l == 0) ? ZOUT : out + NCF;
        mm_gemm<<<grid2, 256>>>(zcur, CF, 4, NNODES, O_GAT, nullptr, HHp, 256,
                                nullptr, nullptr, 0, att_s, att_d,
                                nullptr, nullptr, nullptr);
        gat_agg_kernel<<<WARP_2N, 256>>>(b_gat);
        mm_gemm<<<grid1, 256>>>(AGG, 256, 8, NNODES, O_DEC, b_dec, zdst, CF,
                                nullptr, nullptr, 0, nullptr, nullptr,
                                nullptr, nullptr, nullptr);
    }
    (void)in_sizes; (void)n_in; (void)out_size;
}

// round 7
// speedup vs baseline: 1.9903x; 1.0068x over previous
#include <cuda_runtime.h>
#include <cuda_bf16.h>
#include <cstdint>

#define NNODES 20000
#define NEDGES 640000
#define DINF   92
#define DPAD   128
#define CF     128
#define NCF    (NNODES*CF)

// ---------------- scratch (device globals; no allocation) ----------------
__device__ __align__(16) float g_X[NCF];
__device__ __align__(16) float g_T[NCF];
__device__ __align__(16) float g_Hb[NCF];
__device__ __align__(16) float g_HHb[NNODES*256];
__device__ __align__(16) float g_AGG[NNODES*256];
__device__ __align__(16) float g_ZOUT[NCF];
__device__ __align__(16) float g_NF[NNODES*DPAD];
__device__ __align__(16) uint32_t g_BHI[98304];   // packed bf16-pair weight images
__device__ __align__(16) uint32_t g_BLO[98304];
__device__ __align__(16) float g_AS[NNODES*2];
__device__ __align__(16) float g_AD[NNODES*2];
__device__ __align__(16) float g_S1[CF];
__device__ __align__(16) float g_S2[CF];
__device__ __align__(16) float g_cs[CF];
__device__ __align__(16) float g_cb[CF];
__device__ int   g_cnt[NNODES];
__device__ int   g_rowptr[NNODES+1];
__device__ int   g_cursor[NNODES];
__device__ int   g_csrc[NEDGES];
__device__ int   g_bsum[32];
__device__ int   g_is64;

// ---------------- bf16 hi/lo split + pack ----------------
__device__ __forceinline__ void split_pack(float e0, float e1,
                                           uint32_t& hp, uint32_t& lp) {
    unsigned short h0 = __bfloat16_as_ushort(__float2bfloat16_rn(e0));
    unsigned short h1 = __bfloat16_as_ushort(__float2bfloat16_rn(e1));
    float f0 = __uint_as_float((uint32_t)h0 << 16);
    float f1 = __uint_as_float((uint32_t)h1 << 16);
    unsigned short l0 = __bfloat16_as_ushort(__float2bfloat16_rn(e0 - f0));
    unsigned short l1 = __bfloat16_as_ushort(__float2bfloat16_rn(e1 - f1));
    hp = (uint32_t)h0 | ((uint32_t)h1 << 16);
    lp = (uint32_t)l0 | ((uint32_t)l1 << 16);
}

__device__ __forceinline__ void mma16816(float& d0, float& d1, float& d2, float& d3,
                                         uint32_t a0, uint32_t a1, uint32_t a2, uint32_t a3,
                                         uint32_t b0, uint32_t b1) {
    asm volatile(
        "mma.sync.aligned.m16n8k16.row.col.f32.bf16.bf16.f32 "
        "{%0,%1,%2,%3}, {%4,%5,%6,%7}, {%8,%9}, {%0,%1,%2,%3};"
        : "+f"(d0), "+f"(d1), "+f"(d2), "+f"(d3)
        : "r"(a0), "r"(a1), "r"(a2), "r"(a3), "r"(b0), "r"(b1));
}

__device__ __forceinline__ int edge_src(const void* p, int e) {
    return g_is64 ? (int)((const long long*)p)[e] : ((const int*)p)[e];
}
__device__ __forceinline__ int edge_dst(const void* p, int e) {
    return g_is64 ? (int)((const long long*)p)[NEDGES + e] : ((const int*)p)[NEDGES + e];
}

// ---------------- init: zero counters + stats, detect edge dtype ----------------
__global__ void init_kernel(const void* idx) {
    int i = blockIdx.x * blockDim.x + threadIdx.x;
    if (i < NNODES) g_cnt[i] = 0;
    if (i < CF) { g_S1[i] = 0.f; g_S2[i] = 0.f; }
    if (blockIdx.x == gridDim.x - 1) {   // last block also sniffs dtype
        const int* w = (const int*)idx;
        __shared__ int nz;
        if (threadIdx.x == 0) nz = 0;
        __syncthreads();
        for (int t = threadIdx.x; t < 4096; t += blockDim.x) {
            long long pos = 2LL * t * (NEDGES / 4096) + 1;
            if (pos < 2LL * NEDGES && w[pos] != 0) atomicOr(&nz, 1);
        }
        __syncthreads();
        if (threadIdx.x == 0) g_is64 = (nz == 0) ? 1 : 0;
    }
}

// ---------------- CSR build ----------------
__global__ void hist_kernel(const void* eidx) {
    int e = blockIdx.x * blockDim.x + threadIdx.x;
    if (e < NEDGES) atomicAdd(&g_cnt[edge_dst(eidx, e)], 1);
}
__global__ void scan1_kernel() {
    __shared__ int ws[32];
    int b = blockIdx.x, tid = threadIdx.x, lane = tid & 31, wid = tid >> 5;
    int i = b * 1024 + tid;
    int v = (i < NNODES) ? g_cnt[i] : 0;
    int x = v;
    #pragma unroll
    for (int o = 1; o < 32; o <<= 1) {
        int y = __shfl_up_sync(0xffffffffu, x, o);
        if (lane >= o) x += y;
    }
    if (lane == 31) ws[wid] = x;
    __syncthreads();
    if (wid == 0) {
        int s = ws[lane];
        #pragma unroll
        for (int o = 1; o < 32; o <<= 1) {
            int y = __shfl_up_sync(0xffffffffu, s, o);
            if (lane >= o) s += y;
        }
        ws[lane] = s;
    }
    __syncthreads();
    int incl = x + (wid > 0 ? ws[wid - 1] : 0);
    if (i < NNODES) g_rowptr[i] = incl - v;
    if (tid == 1023) g_bsum[b] = incl;
}
__global__ void scan3_kernel() {   // adds block offsets (computed inline) + total
    int b = blockIdx.x;
    int off = 0;
    #pragma unroll
    for (int j = 0; j < 20; j++) off += (j < b) ? g_bsum[j] : 0;
    int i = b * 1024 + threadIdx.x;
    if (i < NNODES) {
        int r = g_rowptr[i] + off;
        g_rowptr[i] = r;
        g_cursor[i] = r;
    }
    if (b == 0 && threadIdx.x == 0) {
        int t = 0;
        #pragma unroll
        for (int j = 0; j < 20; j++) t += g_bsum[j];
        g_rowptr[NNODES] = t;
    }
}
__global__ void scatter_kernel(const void* eidx) {
    int e = blockIdx.x * blockDim.x + threadIdx.x;
    if (e < NEDGES) {
        int d = edge_dst(eidx, e);
        int s = edge_src(eidx, e);
        int p = atomicAdd(&g_cursor[d], 1);
        g_csrc[p] = s;
    }
}

// ---------------- pad node features 92 -> 128 ----------------
__global__ void pad_nf_kernel(const float* __restrict__ nf) {
    int i = blockIdx.x * blockDim.x + threadIdx.x;
    if (i < NNODES * DPAD) {
        int n = i >> 7, c = i & 127;
        g_NF[i] = (c < DINF) ? nf[n * DINF + c] : 0.f;
    }
}

// ---------------- pack ALL weights in one launch ----------------
// image layout per matrix: [nb][nr 128][kp Kpad/2] u32 pairs
__global__ void packall_kernel(const float* __restrict__ We, const float* __restrict__ W1,
                               const float* __restrict__ W2, const float* __restrict__ Wm,
                               const float* __restrict__ Wv, const float* __restrict__ Wg,
                               const float* __restrict__ Wd) {
    int idx = blockIdx.x * blockDim.x + threadIdx.x;
    const float* W; int Kreal, Kpad, N; uint32_t base; int local;
    if      (idx <  8192) { W = We; Kreal = DINF; Kpad = 128; N = 128; base = 0;     local = idx; }
    else if (idx < 16384) { W = W1; Kreal = 128;  Kpad = 128; N = 128; base = 8192;  local = idx - 8192; }
    else if (idx < 24576) { W = W2; Kreal = 128;  Kpad = 128; N = 128; base = 16384; local = idx - 16384; }
    else if (idx < 32768) { W = Wm; Kreal = 128;  Kpad = 128; N = 128; base = 24576; local = idx - 24576; }
    else if (idx < 40960) { W = Wv; Kreal = 128;  Kpad = 128; N = 128; base = 32768; local = idx - 32768; }
    else if (idx < 57344) { W = Wg; Kreal = 128;  Kpad = 128; N = 256; base = 40960; local = idx - 40960; }
    else if (idx < 73728) { W = Wd; Kreal = 256;  Kpad = 256; N = 128; base = 57344; local = idx - 57344; }
    else return;
    int pairs = Kpad >> 1;
    int n = local / pairs, kp = local - n * pairs;
    int nb = n >> 7, nr = n & 127;
    int k0 = 2 * kp;
    float v0 = (k0     < Kreal) ? W[k0 * N + n]       : 0.f;
    float v1 = (k0 + 1 < Kreal) ? W[(k0 + 1) * N + n] : 0.f;
    uint32_t hp, lp;
    split_pack(v0, v1, hp, lp);
    uint32_t off = base + (uint32_t)nb * 128u * pairs + (uint32_t)nr * pairs + kp;
    g_BHI[off] = hp;
    g_BLO[off] = lp;
}

// ================= bf16 3-product mma.sync GEMM =================
__global__ void __launch_bounds__(256, 2)
mm_gemm(const float* __restrict__ A, int lda, int Kc /* K/32 */, int M,
        uint32_t bbase,
        const float* __restrict__ bias,
        float* __restrict__ Out, int ldo,
        const float* __restrict__ affs, const float* __restrict__ affb,
        int do_stats,
        const float* __restrict__ atts, const float* __restrict__ attd,
        const float* __restrict__ rp_eps, const float* __restrict__ rp_mu,
        float* __restrict__ rp_z)
{
    __shared__ uint32_t AHI[128 * 20], ALO[128 * 20];
    __shared__ uint32_t BHI[128 * 20], BLO[128 * 20];
    __shared__ float    RED1[128], RED2[128];

    const int tid = threadIdx.x, wid = tid >> 5, lane = tid & 31;
    const int g = lane >> 2, tc = lane & 3;
    const int wm = wid >> 2, wn = wid & 3;
    const int r0 = blockIdx.x * 128;
    const int nb = blockIdx.y;
    const int c0 = nb * 128;
    const int pairsK = Kc * 16;
    const uint32_t bimg = bbase + (uint32_t)nb * 128u * pairsK;

    float acc[4][4][4];
    #pragma unroll
    for (int mt = 0; mt < 4; mt++)
        #pragma unroll
        for (int nt = 0; nt < 4; nt++)
            #pragma unroll
            for (int q = 0; q < 4; q++) acc[mt][nt][q] = 0.f;

    for (int c = 0; c < Kc; c++) {
        __syncthreads();
        #pragma unroll
        for (int i = 0; i < 8; i++) {
            int idx = i * 256 + tid;
            int row = idx >> 4, p = idx & 15;
            int grow = r0 + row;
            float2 v = make_float2(0.f, 0.f);
            if (grow < M) {
                v = *(const float2*)&A[(size_t)grow * lda + c * 32 + p * 2];
                if (affs) {
                    int k = c * 32 + p * 2;
                    v.x = fmaxf(affs[k    ] * v.x + affb[k    ], 0.f);
                    v.y = fmaxf(affs[k + 1] * v.y + affb[k + 1], 0.f);
                }
            }
            uint32_t hp, lp;
            split_pack(v.x, v.y, hp, lp);
            AHI[row * 20 + p] = hp;
            ALO[row * 20 + p] = lp;
        }
        #pragma unroll
        for (int i = 0; i < 8; i++) {
            int idx = i * 256 + tid;
            int n = idx >> 4, p = idx & 15;
            uint32_t src = bimg + (uint32_t)n * pairsK + c * 16 + p;
            BHI[n * 20 + p] = g_BHI[src];
            BLO[n * 20 + p] = g_BLO[src];
        }
        __syncthreads();

        #pragma unroll
        for (int prod = 0; prod < 3; prod++) {
            const uint32_t* Ab = (prod == 2) ? ALO : AHI;
            const uint32_t* Bb = (prod == 1) ? BLO : BHI;
            #pragma unroll
            for (int ks = 0; ks < 2; ks++) {
                uint32_t af[4][4], bf[4][2];
                #pragma unroll
                for (int mt = 0; mt < 4; mt++) {
                    int rbase = (wm * 64 + mt * 16 + g) * 20 + ks * 8 + tc;
                    af[mt][0] = Ab[rbase];
                    af[mt][1] = Ab[rbase + 8 * 20];
                    af[mt][2] = Ab[rbase + 4];
                    af[mt][3] = Ab[rbase + 8 * 20 + 4];
                }
                #pragma unroll
                for (int nt = 0; nt < 4; nt++) {
                    int nbase = (wn * 32 + nt * 8 + g) * 20 + ks * 8 + tc;
                    bf[nt][0] = Bb[nbase];
                    bf[nt][1] = Bb[nbase + 4];
                }
                #pragma unroll
                for (int mt = 0; mt < 4; mt++)
                    #pragma unroll
                    for (int nt = 0; nt < 4; nt++)
                        mma16816(acc[mt][nt][0], acc[mt][nt][1],
                                 acc[mt][nt][2], acc[mt][nt][3],
                                 af[mt][0], af[mt][1], af[mt][2], af[mt][3],
                                 bf[nt][0], bf[nt][1]);
            }
        }
    }

    float bc[4][2];
    #pragma unroll
    for (int nt = 0; nt < 4; nt++) {
        int cc = c0 + wn * 32 + nt * 8 + tc * 2;
        bc[nt][0] = bias ? bias[cc]     : 0.f;
        bc[nt][1] = bias ? bias[cc + 1] : 0.f;
    }

    #pragma unroll
    for (int mt = 0; mt < 4; mt++) {
        int row0 = r0 + wm * 64 + mt * 16 + g;
        int row1 = row0 + 8;
        #pragma unroll
        for (int nt = 0; nt < 4; nt++) {
            int cc = c0 + wn * 32 + nt * 8 + tc * 2;
            if (row0 < M) {
                float2 o = make_float2(acc[mt][nt][0] + bc[nt][0],
                                       acc[mt][nt][1] + bc[nt][1]);
                *(float2*)&Out[(size_t)row0 * ldo + cc] = o;
            }
            if (row1 < M) {
                float2 o = make_float2(acc[mt][nt][2] + bc[nt][0],
                                       acc[mt][nt][3] + bc[nt][1]);
                *(float2*)&Out[(size_t)row1 * ldo + cc] = o;
            }
        }
    }

    if (do_stats) {
        if (tid < CF) { RED1[tid] = 0.f; RED2[tid] = 0.f; }
        __syncthreads();
        #pragma unroll
        for (int nt = 0; nt < 4; nt++) {
            int ccl = wn * 32 + nt * 8 + tc * 2;
            float s0 = 0.f, q0 = 0.f, s1 = 0.f, q1 = 0.f;
            #pragma unroll
            for (int mt = 0; mt < 4; mt++) {
                int row0 = r0 + wm * 64 + mt * 16 + g;
                if (row0 < M) {
                    float v0 = acc[mt][nt][0] + bc[nt][0];
                    float v1 = acc[mt][nt][1] + bc[nt][1];
                    s0 += v0; q0 += v0 * v0; s1 += v1; q1 += v1 * v1;
                }
                if (row0 + 8 < M) {
                    float v0 = acc[mt][nt][2] + bc[nt][0];
                    float v1 = acc[mt][nt][3] + bc[nt][1];
                    s0 += v0; q0 += v0 * v0; s1 += v1; q1 += v1 * v1;
                }
            }
            atomicAdd(&RED1[ccl], s0); atomicAdd(&RED2[ccl], q0);
            atomicAdd(&RED1[ccl + 1], s1); atomicAdd(&RED2[ccl + 1], q1);
        }
        __syncthreads();
        if (tid < CF) { atomicAdd(&g_S1[tid], RED1[tid]); atomicAdd(&g_S2[tid], RED2[tid]); }
    }

    if (atts) {
        if (tid < 128) { RED1[tid] = 0.f; RED2[tid] = 0.f; }
        __syncthreads();
        float avs[4][2], avd[4][2];
        #pragma unroll
        for (int nt = 0; nt < 4; nt++) {
            int cc = wn * 32 + nt * 8 + tc * 2;
            avs[nt][0] = atts[nb * CF + cc]; avs[nt][1] = atts[nb * CF + cc + 1];
            avd[nt][0] = attd[nb * CF + cc]; avd[nt][1] = attd[nb * CF + cc + 1];
        }
        #pragma unroll
        for (int mt = 0; mt < 4; mt++) {
            float ss0 = 0.f, sd0 = 0.f, ss1 = 0.f, sd1 = 0.f;
            #pragma unroll
            for (int nt = 0; nt < 4; nt++) {
                ss0 += acc[mt][nt][0] * avs[nt][0] + acc[mt][nt][1] * avs[nt][1];
                sd0 += acc[mt][nt][0] * avd[nt][0] + acc[mt][nt][1] * avd[nt][1];
                ss1 += acc[mt][nt][2] * avs[nt][0] + acc[mt][nt][3] * avs[nt][1];
                sd1 += acc[mt][nt][2] * avd[nt][0] + acc[mt][nt][3] * avd[nt][1];
            }
            int rl = wm * 64 + mt * 16 + g;
            atomicAdd(&RED1[rl], ss0);     atomicAdd(&RED2[rl], sd0);
            atomicAdd(&RED1[rl + 8], ss1); atomicAdd(&RED2[rl + 8], sd1);
        }
        __syncthreads();
        if (tid < 128 && r0 + tid < M) {
            g_AS[(r0 + tid) * 2 + nb] = RED1[tid];
            g_AD[(r0 + tid) * 2 + nb] = RED2[tid];
        }
    }

    if (rp_z) {
        #pragma unroll
        for (int mt = 0; mt < 4; mt++) {
            int row0 = r0 + wm * 64 + mt * 16 + g;
            int row1 = row0 + 8;
            #pragma unroll
            for (int nt = 0; nt < 4; nt++) {
                int cc = wn * 32 + nt * 8 + tc * 2;
                if (row0 < M) {
                    size_t b = (size_t)row0 * CF + cc;
                    rp_z[b]     = rp_eps[b]     * expf(0.5f * (acc[mt][nt][0] + bc[nt][0])) + rp_mu[b];
                    rp_z[b + 1] = rp_eps[b + 1] * expf(0.5f * (acc[mt][nt][1] + bc[nt][1])) + rp_mu[b + 1];
                }
                if (row1 < M) {
                    size_t b = (size_t)row1 * CF + cc;
                    rp_z[b]     = rp_eps[b]     * expf(0.5f * (acc[mt][nt][2] + bc[nt][0])) + rp_mu[b];
                    rp_z[b + 1] = rp_eps[b + 1] * expf(0.5f * (acc[mt][nt][3] + bc[nt][1])) + rp_mu[b + 1];
                }
            }
        }
    }
}

// ---------------- BN finalize (self-resetting stats) ----------------
__global__ void bn_fin_kernel(const float* __restrict__ gam, const float* __restrict__ bet) {
    int c = threadIdx.x;
    if (c < CF) {
        float s1 = g_S1[c], s2 = g_S2[c];
        float mu  = s1 / (float)NNODES;
        float var = s2 / (float)NNODES - mu * mu;
        float a   = gam[c] * rsqrtf(var + 1e-5f);
        g_cs[c] = a;
        g_cb[c] = bet[c] - mu * a;
        g_S1[c] = 0.f;   // ready for next stats accumulation
        g_S2[c] = 0.f;
    }
}

// ---------------- GIN aggregation (optional fused affine+relu on gathered rows) ----
__global__ void gin_agg_kernel(const float* __restrict__ src,
                               const float* __restrict__ cs,
                               const float* __restrict__ cb) {
    int warp = (blockIdx.x * blockDim.x + threadIdx.x) >> 5;
    int lane = threadIdx.x & 31;
    if (warp >= NNODES) return;
    int n = warp;
    const bool aff = (cs != nullptr);
    float4 sc = make_float4(1.f, 1.f, 1.f, 1.f), bb = make_float4(0.f, 0.f, 0.f, 0.f);
    if (aff) {
        sc = *(const float4*)&cs[lane * 4];
        bb = *(const float4*)&cb[lane * 4];
    }
    float4 acc = *(const float4*)&src[n * CF + lane * 4];
    if (aff) {
        acc.x = fmaxf(sc.x * acc.x + bb.x, 0.f);
        acc.y = fmaxf(sc.y * acc.y + bb.y, 0.f);
        acc.z = fmaxf(sc.z * acc.z + bb.z, 0.f);
        acc.w = fmaxf(sc.w * acc.w + bb.w, 0.f);
    }
    int beg = g_rowptr[n], end = g_rowptr[n + 1];
    int i = beg;
    for (; i + 1 < end; i += 2) {
        int s0 = g_csrc[i], s1v = g_csrc[i + 1];
        float4 v0 = *(const float4*)&src[s0 * CF + lane * 4];
        float4 v1 = *(const float4*)&src[s1v * CF + lane * 4];
        if (aff) {
            v0.x = fmaxf(sc.x * v0.x + bb.x, 0.f); v0.y = fmaxf(sc.y * v0.y + bb.y, 0.f);
            v0.z = fmaxf(sc.z * v0.z + bb.z, 0.f); v0.w = fmaxf(sc.w * v0.w + bb.w, 0.f);
            v1.x = fmaxf(sc.x * v1.x + bb.x, 0.f); v1.y = fmaxf(sc.y * v1.y + bb.y, 0.f);
            v1.z = fmaxf(sc.z * v1.z + bb.z, 0.f); v1.w = fmaxf(sc.w * v1.w + bb.w, 0.f);
        }
        acc.x += v0.x + v1.x; acc.y += v0.y + v1.y;
        acc.z += v0.z + v1.z; acc.w += v0.w + v1.w;
    }
    if (i < end) {
        int s0 = g_csrc[i];
        float4 v0 = *(const float4*)&src[s0 * CF + lane * 4];
        if (aff) {
            v0.x = fmaxf(sc.x * v0.x + bb.x, 0.f); v0.y = fmaxf(sc.y * v0.y + bb.y, 0.f);
            v0.z = fmaxf(sc.z * v0.z + bb.z, 0.f); v0.w = fmaxf(sc.w * v0.w + bb.w, 0.f);
        }
        acc.x += v0.x; acc.y += v0.y; acc.z += v0.z; acc.w += v0.w;
    }
    *(float4*)&g_Hb[n * CF + lane * 4] = acc;
}

__device__ __forceinline__ float lrelu(float x) { return x > 0.f ? x : 0.2f * x; }

// ---------------- GAT aggregation: ONE warp per node, BOTH heads ----------------
__global__ void gat_agg_kernel(const float* __restrict__ b_gat) {
    int warp = (blockIdx.x * blockDim.x + threadIdx.x) >> 5;
    int lane = threadIdx.x & 31;
    if (warp >= NNODES) return;
    int n = warp;
    float2 ad  = *(const float2*)&g_AD[n * 2];
    float2 asn = *(const float2*)&g_AS[n * 2];
    float ls0 = lrelu(asn.x + ad.x);
    float ls1 = lrelu(asn.y + ad.y);
    int beg = g_rowptr[n], end = g_rowptr[n + 1];

    // pass 1: segment max per head (incl. self-loop)
    float m0 = ls0, m1 = ls1;
    for (int i = beg + lane; i < end; i += 32) {
        int s = g_csrc[i];
        float2 a = *(const float2*)&g_AS[s * 2];
        m0 = fmaxf(m0, lrelu(a.x + ad.x));
        m1 = fmaxf(m1, lrelu(a.y + ad.y));
    }
    #pragma unroll
    for (int o = 16; o >= 1; o >>= 1) {
        m0 = fmaxf(m0, __shfl_xor_sync(0xffffffffu, m0, o));
        m1 = fmaxf(m1, __shfl_xor_sync(0xffffffffu, m1, o));
    }

    // pass 2: weighted accumulate (all lanes lockstep over edges)
    float w0 = expf(ls0 - m0), w1 = expf(ls1 - m1);
    float s0 = w0, s1 = w1;
    const float* hn = &g_HHb[n * 256];
    float4 h0 = *(const float4*)&hn[lane * 4];
    float4 h1 = *(const float4*)&hn[128 + lane * 4];
    float4 acc0 = make_float4(w0 * h0.x, w0 * h0.y, w0 * h0.z, w0 * h0.w);
    float4 acc1 = make_float4(w1 * h1.x, w1 * h1.y, w1 * h1.z, w1 * h1.w);
    int i = beg;
    for (; i + 1 < end; i += 2) {
        int sa = g_csrc[i], sb = g_csrc[i + 1];
        float2 aa = *(const float2*)&g_AS[sa * 2];
        float2 ab = *(const float2*)&g_AS[sb * 2];
        float ea0 = expf(lrelu(aa.x + ad.x) - m0), ea1 = expf(lrelu(aa.y + ad.y) - m1);
        float eb0 = expf(lrelu(ab.x + ad.x) - m0), eb1 = expf(lrelu(ab.y + ad.y) - m1);
        s0 += ea0 + eb0; s1 += ea1 + eb1;
        const float* ha = &g_HHb[sa * 256];
        const float* hb = &g_HHb[sb * 256];
        float4 va0 = *(const float4*)&ha[lane * 4];
        float4 va1 = *(const float4*)&ha[128 + lane * 4];
        float4 vb0 = *(const float4*)&hb[lane * 4];
        float4 vb1 = *(const float4*)&hb[128 + lane * 4];
        acc0.x += ea0 * va0.x + eb0 * vb0.x; acc0.y += ea0 * va0.y + eb0 * vb0.y;
        acc0.z += ea0 * va0.z + eb0 * vb0.z; acc0.w += ea0 * va0.w + eb0 * vb0.w;
        acc1.x += ea1 * va1.x + eb1 * vb1.x; acc1.y += ea1 * va1.y + eb1 * vb1.y;
        acc1.z += ea1 * va1.z + eb1 * vb1.z; acc1.w += ea1 * va1.w + eb1 * vb1.w;
    }
    if (i < end) {
        int sa = g_csrc[i];
        float2 aa = *(const float2*)&g_AS[sa * 2];
        float ea0 = expf(lrelu(aa.x + ad.x) - m0), ea1 = expf(lrelu(aa.y + ad.y) - m1);
        s0 += ea0; s1 += ea1;
        const float* ha = &g_HHb[sa * 256];
        float4 va0 = *(const float4*)&ha[lane * 4];
        float4 va1 = *(const float4*)&ha[128 + lane * 4];
        acc0.x += ea0 * va0.x; acc0.y += ea0 * va0.y;
        acc0.z += ea0 * va0.z; acc0.w += ea0 * va0.w;
        acc1.x += ea1 * va1.x; acc1.y += ea1 * va1.y;
        acc1.z += ea1 * va1.z; acc1.w += ea1 * va1.w;
    }
    float i0 = 1.f / s0, i1 = 1.f / s1;
    float4 bg0 = *(const float4*)&b_gat[lane * 4];
    float4 bg1 = *(const float4*)&b_gat[128 + lane * 4];
    float4 o0 = make_float4(acc0.x * i0 + bg0.x, acc0.y * i0 + bg0.y,
                            acc0.z * i0 + bg0.z, acc0.w * i0 + bg0.w);
    float4 o1 = make_float4(acc1.x * i1 + bg1.x, acc1.y * i1 + bg1.y,
                            acc1.z * i1 + bg1.z, acc1.w * i1 + bg1.w);
    *(float4*)&g_AGG[n * 256 + lane * 4]       = o0;
    *(float4*)&g_AGG[n * 256 + 128 + lane * 4] = o1;
}

// ---------------- host orchestration ----------------
extern "C" void kernel_launch(void* const* d_in, const int* in_sizes, int n_in,
                              void* d_out, int out_size) {
    const float* nf     = (const float*)d_in[0];
    const void*  eidx   =               d_in[1];
    const float* eps    = (const float*)d_in[2];
    const float* W_emb  = (const float*)d_in[3];
    const float* b_emb  = (const float*)d_in[4];
    const float* g_embp = (const float*)d_in[5];
    const float* be_emb = (const float*)d_in[6];
    const float* W1     = (const float*)d_in[7];
    const float* b1     = (const float*)d_in[8];
    const float* g1     = (const float*)d_in[9];
    const float* be1    = (const float*)d_in[10];
    const float* W2     = (const float*)d_in[11];
    const float* b2     = (const float*)d_in[12];
    const float* W_mu   = (const float*)d_in[13];
    const float* b_mu   = (const float*)d_in[14];
    const float* W_var  = (const float*)d_in[15];
    const float* b_var  = (const float*)d_in[16];
    const float* W_gat  = (const float*)d_in[17];
    const float* att_s  = (const float*)d_in[18];
    const float* att_d  = (const float*)d_in[19];
    const float* b_gat  = (const float*)d_in[20];
    const float* W_dec  = (const float*)d_in[21];
    const float* b_dec  = (const float*)d_in[22];
    float* out = (float*)d_out;

    float *X, *T, *Hb, *HHp, *AGG, *ZOUT, *CS, *CB, *NF;
    cudaGetSymbolAddress((void**)&X,    g_X);
    cudaGetSymbolAddress((void**)&T,    g_T);
    cudaGetSymbolAddress((void**)&Hb,   g_Hb);
    cudaGetSymbolAddress((void**)&HHp,  g_HHb);
    cudaGetSymbolAddress((void**)&AGG,  g_AGG);
    cudaGetSymbolAddress((void**)&ZOUT, g_ZOUT);
    cudaGetSymbolAddress((void**)&CS,   g_cs);
    cudaGetSymbolAddress((void**)&CB,   g_cb);
    cudaGetSymbolAddress((void**)&NF,   g_NF);

    const int GX = (NNODES + 127) / 128;   // 157
    dim3 grid1(GX, 1), grid2(GX, 2);
    const int EB = (NEDGES + 255) / 256;
    const int NB = (NNODES + 255) / 256;
    const int WARP_N = (NNODES * 32 + 255) / 256;   // 1 warp / node
    const int PB  = (NNODES * DPAD + 255) / 256;

    const uint32_t O_EMB = 0, O_W1 = 8192, O_W2 = 16384, O_MU = 24576,
                   O_VAR = 32768, O_GAT = 40960, O_DEC = 57344;

    // pack all weights in one launch
    packall_kernel<<<(73728 + 255) / 256, 256>>>(W_emb, W1, W2, W_mu, W_var, W_gat, W_dec);

    // CSR build (init also zeros BN stats + detects dtype)
    init_kernel<<<NB, 256>>>(eidx);
    hist_kernel<<<EB, 256>>>(eidx);
    scan1_kernel<<<20, 1024>>>();
    scan3_kernel<<<20, 1024>>>();
    scatter_kernel<<<EB, 256>>>(eidx);

    // atom embedding: T = nf@W_emb+b (stats); bn_fin -> cs/cb (and resets stats)
    pad_nf_kernel<<<PB, 256>>>(nf);
    mm_gemm<<<grid1, 256>>>(NF, DPAD, 4, NNODES, O_EMB, b_emb, T, CF,
                            nullptr, nullptr, 1, nullptr, nullptr,
                            nullptr, nullptr, nullptr);
    bn_fin_kernel<<<1, 128>>>(g_embp, be_emb);

    // GIN layer 0: agg applies emb-BN affine+relu to gathered rows of T
    gin_agg_kernel<<<WARP_N, 256>>>(T, CS, CB);
    mm_gemm<<<grid1, 256>>>(Hb, CF, 4, NNODES, O_W1, b1, T, CF,
                            nullptr, nullptr, 1, nullptr, nullptr,
                            nullptr, nullptr, nullptr);
    bn_fin_kernel<<<1, 128>>>(g1, be1);
    mm_gemm<<<grid1, 256>>>(T, CF, 4, NNODES, O_W2, b2, X, CF,
                            CS, CB, 0, nullptr, nullptr,
                            nullptr, nullptr, nullptr);

    // GIN layer 1: raw x (no activation between layers)
    gin_agg_kernel<<<WARP_N, 256>>>(X, nullptr, nullptr);
    mm_gemm<<<grid1, 256>>>(Hb, CF, 4, NNODES, O_W1, b1, T, CF,
                            nullptr, nullptr, 1, nullptr, nullptr,
                            nullptr, nullptr, nullptr);
    bn_fin_kernel<<<1, 128>>>(g1, be1);
    mm_gemm<<<grid1, 256>>>(T, CF, 4, NNODES, O_W2, b2, X, CF,
                            CS, CB, 0, nullptr, nullptr,
                            nullptr, nullptr, nullptr);

    // VAE heads: mu, then logvar with fused z
    mm_gemm<<<grid1, 256>>>(X, CF, 4, NNODES, O_MU, b_mu, out + 2 * NCF, CF,
                            nullptr, nullptr, 0, nullptr, nullptr,
                            nullptr, nullptr, nullptr);
    mm_gemm<<<grid1, 256>>>(X, CF, 4, NNODES, O_VAR, b_var, out + 3 * NCF, CF,
                            nullptr, nullptr, 0, nullptr, nullptr,
                            eps, out + 2 * NCF, out);

    // GAT decoder x2 (shared weights)
    for (int l = 0; l < 2; l++) {
        const float* zcur = (l == 0) ? out : ZOUT;
        float* zdst       = (l == 0) ? ZOUT : out + NCF;
        mm_gemm<<<grid2, 256>>>(zcur, CF, 4, NNODES, O_GAT, nullptr, HHp, 256,
                                nullptr, nullptr, 0, att_s, att_d,
                                nullptr, nullptr, nullptr);
        gat_agg_kernel<<<WARP_N, 256>>>(b_gat);
        mm_gemm<<<grid1, 256>>>(AGG, 256, 8, NNODES, O_DEC, b_dec, zdst, CF,
                                nullptr, nullptr, 0, nullptr, nullptr,
                                nullptr, nullptr, nullptr);
    }
    (void)in_sizes; (void)n_in; (void)out_size;
}